// round 7
// baseline (speedup 1.0000x reference)
#include <cuda_runtime.h>
#include <cuda_bf16.h>
#include <cstdint>
#include <math.h>

using bf16 = __nv_bfloat16;

// ---------------- problem constants ----------------
constexpr int Bd  = 4;
constexpr int S1  = 64;
constexpr int S2  = 256;
constexpr int D   = 256;
constexpr int Hh  = 8;
constexpr int HD  = 32;
constexpr int Fd  = 1024;
constexpr int TOK = Bd * S1 * S2;     // 65536
constexpr int BN_ = Bd * S1;          // 256
constexpr int SP  = S2 + 2;           // padded time length 258

// ---------------- scratch (device globals) ----------------
__device__ bf16  g_xph[BN_ * SP * D];
__device__ bf16  g_xpl[BN_ * SP * D];
__device__ bf16  g_qh [TOK * D];
__device__ bf16  g_ql [TOK * D];
__device__ bf16  g_kh [TOK * D];
__device__ bf16  g_kl [TOK * D];
__device__ bf16  g_vh [TOK * D];
__device__ bf16  g_aoh[TOK * D];
__device__ bf16  g_aol[TOK * D];
__device__ float g_s  [TOK * D];
__device__ float g_h  [TOK * D];
__device__ bf16  g_hh [TOK * D];
__device__ bf16  g_hl [TOK * D];
__device__ bf16  g_ffh[TOK * Fd];
__device__ bf16  g_ffl[TOK * Fd];
// transposed weights, hi/lo
__device__ bf16 g_wqh[D * 3 * D], g_wql[D * 3 * D];
__device__ bf16 g_wkh[D * 3 * D], g_wkl[D * 3 * D];
__device__ bf16 g_wvh[D * D],     g_wvl[D * D];
__device__ bf16 g_woh[D * D],     g_wol[D * D];
__device__ bf16 g_w1h[Fd * D],    g_w1l[Fd * D];
__device__ bf16 g_w2h[D * Fd],    g_w2l[D * Fd];

// ---------------- helpers ----------------
__device__ __forceinline__ uint32_t smem_to_u32(const void* p) {
    uint32_t a;
    asm("{ .reg .u64 t; cvta.to.shared.u64 t, %1; cvt.u32.u64 %0, t; }" : "=r"(a) : "l"(p));
    return a;
}
#define CP_ASYNC16(s, g) \
    asm volatile("cp.async.cg.shared.global [%0], [%1], 16;" :: "r"((uint32_t)(s)), "l"(g))
#define CP_ASYNC_COMMIT() asm volatile("cp.async.commit_group;" ::: "memory")

__device__ __forceinline__ void ldsm4(uint32_t addr, uint32_t& r0, uint32_t& r1,
                                      uint32_t& r2, uint32_t& r3) {
    asm volatile("ldmatrix.sync.aligned.m8n8.x4.shared.b16 {%0,%1,%2,%3}, [%4];"
                 : "=r"(r0), "=r"(r1), "=r"(r2), "=r"(r3) : "r"(addr));
}
__device__ __forceinline__ void ldsm4t(uint32_t addr, uint32_t& r0, uint32_t& r1,
                                       uint32_t& r2, uint32_t& r3) {
    asm volatile("ldmatrix.sync.aligned.m8n8.x4.trans.shared.b16 {%0,%1,%2,%3}, [%4];"
                 : "=r"(r0), "=r"(r1), "=r"(r2), "=r"(r3) : "r"(addr));
}
__device__ __forceinline__ void mma_bf16(float* c, const uint32_t* a, const uint32_t* b) {
    asm volatile("mma.sync.aligned.m16n8k16.row.col.f32.bf16.bf16.f32 "
                 "{%0,%1,%2,%3}, {%4,%5,%6,%7}, {%8,%9}, {%0,%1,%2,%3};"
                 : "+f"(c[0]), "+f"(c[1]), "+f"(c[2]), "+f"(c[3])
                 : "r"(a[0]), "r"(a[1]), "r"(a[2]), "r"(a[3]), "r"(b[0]), "r"(b[1]));
}
__device__ __forceinline__ void split_bf16(float v, bf16& h, bf16& l) {
    h = __float2bfloat16(v);
    l = __float2bfloat16(v - __bfloat162float(h));
}
__device__ __forceinline__ uint32_t pack2(bf16 a, bf16 b) {
    __nv_bfloat162 p; p.x = a; p.y = b;
    return *(uint32_t*)&p;
}
// 64B-row swizzle: 4 16B columns, rotate by (row>>1)&3
__device__ __forceinline__ uint32_t sw64(int row, int c) {
    return (uint32_t)(row * 64 + ((c ^ ((row >> 1) & 3)) << 4));
}

// ---------------------------------------------------------------------------
// Tensor-core GEMM: 128x256 CTA tile, 512 threads (16 warps, 2x8), BK=32,
// split-bf16 3-pass, 3-stage cp.async pipeline, one barrier per chunk.
// Per-z runtime config (merges Q/K/V into one launch).
// stage (48KB): [Ah 8K][Al 8K][Bh 16K][Bl 16K]
// epi: 0 = bias*scl -> fp32 ; 1 = +R -> fp32 ; 2 = leaky -> bf16 hi/lo ;
//      3 = bf16 hi/lo ; 4 = bf16 hi only
// ---------------------------------------------------------------------------
struct GCfg {
    const bf16* Bh; const bf16* Bl;
    const float* bias; float scl;
    float* Cf; bf16* Ch; bf16* Cl;
    int epi; int ldB; int Ktap; int ntaps; int tapbase;
};

constexpr int GSTAGE = 49152;
constexpr int GSMEM  = 3 * GSTAGE;   // 147456

template<bool CONV>
__global__ __launch_bounds__(512, 1)
void gemm_tc(const bf16* __restrict__ Ah, const bf16* __restrict__ Al, int ldA,
             const float* __restrict__ R, int Nt,
             GCfg c0, GCfg c1, GCfg c2)
{
    extern __shared__ char smem[];
    const uint32_t sbase = smem_to_u32(smem);
    const int tid = threadIdx.x, wid = tid >> 5, lane = tid & 31;
    const int m0 = blockIdx.y * 128, n0 = blockIdx.x * 256;

    const GCfg cf = (blockIdx.z == 0) ? c0 : ((blockIdx.z == 1) ? c1 : c2);

    int rowbase;
    if (CONV) { const int bn = m0 >> 8; const int t0 = m0 & 255; rowbase = bn * SP + t0 + cf.tapbase; }
    else      { rowbase = m0; }

    const int kcpt = cf.Ktap >> 5;
    const int nch  = cf.ntaps * kcpt;
    const int c4   = tid & 3;            // 16B column 0..3
    const int rwA  = tid >> 2;           // row 0..127

    auto load_chunk = [&](int c, int stage) {
        const int tap = c / kcpt;
        const int kt  = (c - tap * kcpt) << 5;
        const size_t aoff = (size_t)(rowbase + tap) * ldA + kt + c4 * 8;
        const size_t boff = (size_t)n0 * cf.ldB + (size_t)tap * cf.Ktap + kt + c4 * 8;
        const uint32_t st = sbase + stage * GSTAGE;
        {
            const uint32_t so = sw64(rwA, c4);
            CP_ASYNC16(st +        so, Ah + aoff + (size_t)rwA * ldA);
            CP_ASYNC16(st + 8192 + so, Al + aoff + (size_t)rwA * ldA);
        }
#pragma unroll
        for (int i = 0; i < 2; i++) {
            const int row = rwA + i * 128;
            const uint32_t so = sw64(row, c4);
            CP_ASYNC16(st + 16384 + so, cf.Bh + boff + (size_t)row * cf.ldB);
            CP_ASYNC16(st + 32768 + so, cf.Bl + boff + (size_t)row * cf.ldB);
        }
        CP_ASYNC_COMMIT();
    };

    load_chunk(0, 0);
    load_chunk(1, 1);

    const int wm  = wid & 1,  wn  = wid >> 1;      // 2 x 8 warps
    const int m0w = wm * 64,  n0w = wn * 32;
    const int tq  = lane >> 3, rin = lane & 7;
    const int aRow = m0w + (tq & 1) * 8 + rin;
    const int akh  = tq >> 1;
    const int bRow = n0w + (tq >> 1) * 8 + rin;
    const int bkh  = tq & 1;

    float acc[4][4][4];
#pragma unroll
    for (int i = 0; i < 4; i++)
#pragma unroll
        for (int j = 0; j < 4; j++)
#pragma unroll
            for (int r = 0; r < 4; r++) acc[i][j][r] = 0.f;

    for (int c = 0; c < nch; c++) {
        if (c + 1 < nch) asm volatile("cp.async.wait_group 1;" ::: "memory");
        else             asm volatile("cp.async.wait_group 0;" ::: "memory");
        __syncthreads();
        if (c + 2 < nch) load_chunk(c + 2, (c + 2) % 3);

        const uint32_t Ab = sbase + (c % 3) * GSTAGE;
        const uint32_t Bb = Ab + 16384;

#pragma unroll
        for (int ks = 0; ks < 2; ks++) {
            uint32_t ah[4][4], al[4][4], bh[4][2], bl[4][2];
#pragma unroll
            for (int mt = 0; mt < 4; mt++) {
                const int r = aRow + mt * 16;
                const uint32_t ad = Ab + sw64(r, ks * 2 + akh);
                ldsm4(ad,         ah[mt][0], ah[mt][1], ah[mt][2], ah[mt][3]);
                ldsm4(ad + 8192,  al[mt][0], al[mt][1], al[mt][2], al[mt][3]);
            }
#pragma unroll
            for (int nt2 = 0; nt2 < 2; nt2++) {
                const int r = bRow + nt2 * 16;
                const uint32_t bd = Bb + sw64(r, ks * 2 + bkh);
                uint32_t r0, r1, r2, r3;
                ldsm4(bd, r0, r1, r2, r3);
                bh[nt2 * 2][0] = r0; bh[nt2 * 2][1] = r1;
                bh[nt2 * 2 + 1][0] = r2; bh[nt2 * 2 + 1][1] = r3;
                ldsm4(bd + 16384, r0, r1, r2, r3);
                bl[nt2 * 2][0] = r0; bl[nt2 * 2][1] = r1;
                bl[nt2 * 2 + 1][0] = r2; bl[nt2 * 2 + 1][1] = r3;
            }
#pragma unroll
            for (int mt = 0; mt < 4; mt++)
#pragma unroll
                for (int nt = 0; nt < 4; nt++) {
                    mma_bf16(acc[mt][nt], ah[mt], bh[nt]);
                    mma_bf16(acc[mt][nt], ah[mt], bl[nt]);
                    mma_bf16(acc[mt][nt], al[mt], bh[nt]);
                }
        }
    }

    const int erow = lane >> 2;
    const int ecol = (lane & 3) * 2;
    const int epi = cf.epi;
#pragma unroll
    for (int mt = 0; mt < 4; mt++) {
#pragma unroll
        for (int nt = 0; nt < 4; nt++) {
            const int col = n0 + n0w + nt * 8 + ecol;
            const float2 bi = *(const float2*)&cf.bias[col];
#pragma unroll
            for (int half = 0; half < 2; half++) {
                const int row = m0 + m0w + mt * 16 + erow + half * 8;
                float v0 = (acc[mt][nt][half * 2 + 0] + bi.x) * cf.scl;
                float v1 = (acc[mt][nt][half * 2 + 1] + bi.y) * cf.scl;
                if (epi == 1) {
                    const float2 rr = *(const float2*)&R[(size_t)row * Nt + col];
                    v0 += rr.x; v1 += rr.y;
                }
                if (epi >= 2) {
                    if (epi == 2) {
                        v0 = v0 > 0.f ? v0 : 0.01f * v0;
                        v1 = v1 > 0.f ? v1 : 0.01f * v1;
                    }
                    bf16 h0, l0, h1, l1;
                    split_bf16(v0, h0, l0); split_bf16(v1, h1, l1);
                    *(uint32_t*)&cf.Ch[(size_t)row * Nt + col] = pack2(h0, h1);
                    if (epi != 4)
                        *(uint32_t*)&cf.Cl[(size_t)row * Nt + col] = pack2(l0, l1);
                } else {
                    float2 o; o.x = v0; o.y = v1;
                    *(float2*)&cf.Cf[(size_t)row * Nt + col] = o;
                }
            }
        }
    }
}

// ---------------------------------------------------------------------------
// pad + split x into bf16 hi/lo padded buffer [bn][258][256]
// ---------------------------------------------------------------------------
__global__ __launch_bounds__(256)
void padcvt_x(const float* __restrict__ x, bf16* __restrict__ xh, bf16* __restrict__ xl)
{
    const size_t i = (size_t)blockIdx.x * 256 + threadIdx.x;
    const int d = (int)(i & 255);
    const size_t rest = i >> 8;
    const int t = (int)(rest % SP);
    const size_t bn = rest / SP;
    float v = 0.f;
    if (t >= 1 && t <= S2) v = x[(bn * S2 + (t - 1)) * D + d];
    bf16 h, l; split_bf16(v, h, l);
    xh[i] = h; xl[i] = l;
}

// ---------------------------------------------------------------------------
// fused weight transpose+split: 6 weights in one launch (1024 32x32 tiles)
// ---------------------------------------------------------------------------
__global__ __launch_bounds__(256)
void wtall(const float* __restrict__ Wq, const float* __restrict__ Wk,
           const float* __restrict__ Wv, const float* __restrict__ Wo,
           const float* __restrict__ W1, const float* __restrict__ W2,
           bf16* wqh, bf16* wql, bf16* wkh, bf16* wkl,
           bf16* wvh, bf16* wvl, bf16* woh, bf16* wol,
           bf16* w1h, bf16* w1l, bf16* w2h, bf16* w2l)
{
    __shared__ float ts[32][33];
    const int t = blockIdx.x;
    const float* W; bf16 *Bh, *Bl; int K, N, lt;
    if      (t < 192) { W = Wq; Bh = wqh; Bl = wql; K = 768;  N = 256;  lt = t; }
    else if (t < 384) { W = Wk; Bh = wkh; Bl = wkl; K = 768;  N = 256;  lt = t - 192; }
    else if (t < 448) { W = Wv; Bh = wvh; Bl = wvl; K = 256;  N = 256;  lt = t - 384; }
    else if (t < 512) { W = Wo; Bh = woh; Bl = wol; K = 256;  N = 256;  lt = t - 448; }
    else if (t < 768) { W = W1; Bh = w1h; Bl = w1l; K = 256;  N = 1024; lt = t - 512; }
    else              { W = W2; Bh = w2h; Bl = w2l; K = 1024; N = 256;  lt = t - 768; }
    const int ntn = N / 32;
    const int n0 = (lt % ntn) * 32, k0 = (lt / ntn) * 32;
    const int tx = threadIdx.x, ty = threadIdx.y;   // 32 x 8
#pragma unroll
    for (int j = 0; j < 4; j++)
        ts[ty + j * 8][tx] = W[(size_t)(k0 + ty + j * 8) * N + n0 + tx];
    __syncthreads();
#pragma unroll
    for (int j = 0; j < 4; j++) {
        const float v = ts[tx][ty + j * 8];
        bf16 h, l; split_bf16(v, h, l);
        const size_t o = (size_t)(n0 + ty + j * 8) * K + k0 + tx;
        Bh[o] = h; Bl[o] = l;
    }
}

// ---------------------------------------------------------------------------
// Flash attention on tensor cores. One block per (b,n,h); 8 warps x 32 rows.
// QK scores: 3-pass split-bf16. PV: single-pass bf16; V B-frags come from
// row-major V smem via ldmatrix.x4.trans (no transpose copy, no V-lo).
// smem: Qh Ql Kh Kl Vh, 5 x 20480 (rows stride 80B -> conflict-free)
// ---------------------------------------------------------------------------
constexpr int ATT_SMEM = 5 * 20480;   // 102400

__global__ __launch_bounds__(256, 2)
void attn_tc(const bf16* __restrict__ qh, const bf16* __restrict__ ql,
             const bf16* __restrict__ kh, const bf16* __restrict__ kl,
             const bf16* __restrict__ vh,
             bf16* __restrict__ oh, bf16* __restrict__ ol)
{
    extern __shared__ char smem[];
    const uint32_t sb = smem_to_u32(smem);
    const uint32_t Qh = sb, Ql_ = sb + 20480, Kh = sb + 40960, Kl_ = sb + 61440;
    const uint32_t Vh = sb + 81920;

    const int tid = threadIdx.x, wid = tid >> 5, lane = tid & 31;
    const int h = blockIdx.x & 7, bn = blockIdx.x >> 3;
    const size_t gbase = (size_t)bn * 256 * 256 + h * 32;

    for (int idx = tid; idx < 1024; idx += 256) {
        const int row = idx >> 2, c = idx & 3;
        const size_t g = gbase + (size_t)row * 256 + c * 8;
        const uint32_t so = row * 80 + c * 16;
        CP_ASYNC16(Qh  + so, qh + g);
        CP_ASYNC16(Ql_ + so, ql + g);
        CP_ASYNC16(Kh  + so, kh + g);
        CP_ASYNC16(Kl_ + so, kl + g);
        CP_ASYNC16(Vh  + so, vh + g);
    }
    CP_ASYNC_COMMIT();
    asm volatile("cp.async.wait_group 0;" ::: "memory");
    __syncthreads();

    const int tq = lane >> 3, rin = lane & 7;
    const int aR  = (tq & 1) * 8 + rin;
    const int akh = tq >> 1;
    const int bR  = (tq >> 1) * 8 + rin;
    const int bkh = tq & 1;
    // trans-ldsm lane mapping for V (B-frags from row-major [s][d])
    const int vrow  = (lane & 7) + ((lane >> 3) & 1) * 8;
    const int vcolb = ((lane >> 4) & 1) * 16;

    uint32_t qfh[2][2][4], qfl[2][2][4];
#pragma unroll
    for (int mt = 0; mt < 2; mt++)
#pragma unroll
        for (int ks = 0; ks < 2; ks++) {
            const uint32_t ad = Qh + (uint32_t)((wid * 32 + mt * 16 + aR) * 80)
                              + (uint32_t)((ks * 2 + akh) * 16);
            ldsm4(ad,          qfh[mt][ks][0], qfh[mt][ks][1], qfh[mt][ks][2], qfh[mt][ks][3]);
            ldsm4(ad + 20480,  qfl[mt][ks][0], qfl[mt][ks][1], qfl[mt][ks][2], qfl[mt][ks][3]);
        }

    float O[2][4][4];
#pragma unroll
    for (int mt = 0; mt < 2; mt++)
#pragma unroll
        for (int j = 0; j < 4; j++)
#pragma unroll
            for (int r = 0; r < 4; r++) O[mt][j][r] = 0.f;
    float mrow[2][2] = { {-1e30f, -1e30f}, {-1e30f, -1e30f} };
    float lrow[2][2] = { {0.f, 0.f}, {0.f, 0.f} };

    for (int s0 = 0; s0 < 256; s0 += 64) {
        float acc[2][8][4];
#pragma unroll
        for (int mt = 0; mt < 2; mt++)
#pragma unroll
            for (int j = 0; j < 8; j++)
#pragma unroll
                for (int r = 0; r < 4; r++) acc[mt][j][r] = 0.f;

#pragma unroll
        for (int ks = 0; ks < 2; ks++) {
            uint32_t kbh[8][2], kbl[8][2];
#pragma unroll
            for (int g = 0; g < 4; g++) {
                const uint32_t kd = Kh + (uint32_t)((s0 + g * 16 + bR) * 80)
                                  + (uint32_t)((ks * 2 + bkh) * 16);
                uint32_t r0, r1, r2, r3;
                ldsm4(kd, r0, r1, r2, r3);
                kbh[g * 2][0] = r0; kbh[g * 2][1] = r1;
                kbh[g * 2 + 1][0] = r2; kbh[g * 2 + 1][1] = r3;
                ldsm4(kd + 20480, r0, r1, r2, r3);
                kbl[g * 2][0] = r0; kbl[g * 2][1] = r1;
                kbl[g * 2 + 1][0] = r2; kbl[g * 2 + 1][1] = r3;
            }
#pragma unroll
            for (int mt = 0; mt < 2; mt++)
#pragma unroll
                for (int j = 0; j < 8; j++) {
                    mma_bf16(acc[mt][j], qfh[mt][ks], kbh[j]);
                    mma_bf16(acc[mt][j], qfh[mt][ks], kbl[j]);
                    mma_bf16(acc[mt][j], qfl[mt][ks], kbh[j]);
                }
        }

#pragma unroll
        for (int mt = 0; mt < 2; mt++) {
            float mxA = -1e30f, mxB = -1e30f;
#pragma unroll
            for (int j = 0; j < 8; j++) {
                mxA = fmaxf(mxA, fmaxf(acc[mt][j][0], acc[mt][j][1]));
                mxB = fmaxf(mxB, fmaxf(acc[mt][j][2], acc[mt][j][3]));
            }
            mxA = fmaxf(mxA, __shfl_xor_sync(0xffffffffu, mxA, 1));
            mxA = fmaxf(mxA, __shfl_xor_sync(0xffffffffu, mxA, 2));
            mxB = fmaxf(mxB, __shfl_xor_sync(0xffffffffu, mxB, 1));
            mxB = fmaxf(mxB, __shfl_xor_sync(0xffffffffu, mxB, 2));
            const float mnA = fmaxf(mrow[mt][0], mxA);
            const float mnB = fmaxf(mrow[mt][1], mxB);
            const float fA = __expf(mrow[mt][0] - mnA);
            const float fB = __expf(mrow[mt][1] - mnB);
            mrow[mt][0] = mnA; mrow[mt][1] = mnB;
            float sA = 0.f, sB = 0.f;
#pragma unroll
            for (int j = 0; j < 8; j++) {
                acc[mt][j][0] = __expf(acc[mt][j][0] - mnA);
                acc[mt][j][1] = __expf(acc[mt][j][1] - mnA);
                acc[mt][j][2] = __expf(acc[mt][j][2] - mnB);
                acc[mt][j][3] = __expf(acc[mt][j][3] - mnB);
                sA += acc[mt][j][0] + acc[mt][j][1];
                sB += acc[mt][j][2] + acc[mt][j][3];
            }
            lrow[mt][0] = lrow[mt][0] * fA + sA;
            lrow[mt][1] = lrow[mt][1] * fB + sB;
#pragma unroll
            for (int j = 0; j < 4; j++) {
                O[mt][j][0] *= fA; O[mt][j][1] *= fA;
                O[mt][j][2] *= fB; O[mt][j][3] *= fB;
            }
        }

        // ---- O += P * V (single-pass; V B-frags via ldmatrix.trans) ----
#pragma unroll
        for (int kt = 0; kt < 4; kt++) {
            uint32_t vb[4][2];
#pragma unroll
            for (int nb = 0; nb < 2; nb++) {
                const uint32_t vd = Vh + (uint32_t)((s0 + kt * 16 + vrow) * 80)
                                  + (uint32_t)(nb * 32 + vcolb);
                uint32_t r0, r1, r2, r3;
                ldsm4t(vd, r0, r1, r2, r3);
                vb[nb * 2][0] = r0; vb[nb * 2][1] = r1;
                vb[nb * 2 + 1][0] = r2; vb[nb * 2 + 1][1] = r3;
            }
#pragma unroll
            for (int mt = 0; mt < 2; mt++) {
                uint32_t ph[4];
#pragma unroll
                for (int half = 0; half < 2; half++) {
                    const int j = 2 * kt + half;
                    ph[half * 2 + 0] = pack2(__float2bfloat16(acc[mt][j][0]),
                                             __float2bfloat16(acc[mt][j][1]));
                    ph[half * 2 + 1] = pack2(__float2bfloat16(acc[mt][j][2]),
                                             __float2bfloat16(acc[mt][j][3]));
                }
#pragma unroll
                for (int j2 = 0; j2 < 4; j2++)
                    mma_bf16(O[mt][j2], ph, vb[j2]);
            }
        }
    }

#pragma unroll
    for (int mt = 0; mt < 2; mt++) {
        float lA = lrow[mt][0], lB = lrow[mt][1];
        lA += __shfl_xor_sync(0xffffffffu, lA, 1);
        lA += __shfl_xor_sync(0xffffffffu, lA, 2);
        lB += __shfl_xor_sync(0xffffffffu, lB, 1);
        lB += __shfl_xor_sync(0xffffffffu, lB, 2);
        const float invA = 1.f / lA, invB = 1.f / lB;
        const int rowA = wid * 32 + mt * 16 + (lane >> 2);
        const size_t gA = gbase + (size_t)rowA * 256;
        const size_t gB = gA + (size_t)8 * 256;
#pragma unroll
        for (int j2 = 0; j2 < 4; j2++) {
            const int col = j2 * 8 + (lane & 3) * 2;
            const float a0 = O[mt][j2][0] * invA, a1 = O[mt][j2][1] * invA;
            const float b0 = O[mt][j2][2] * invB, b1 = O[mt][j2][3] * invB;
            bf16 h0, l0, h1, l1;
            split_bf16(a0, h0, l0); split_bf16(a1, h1, l1);
            *(uint32_t*)&oh[gA + col] = pack2(h0, h1);
            *(uint32_t*)&ol[gA + col] = pack2(l0, l1);
            split_bf16(b0, h0, l0); split_bf16(b1, h1, l1);
            *(uint32_t*)&oh[gB + col] = pack2(h0, h1);
            *(uint32_t*)&ol[gB + col] = pack2(l0, l1);
        }
    }
}

// ---------------------------------------------------------------------------
// LayerNorm (D=256). Optionally emits bf16 hi/lo of the normalized output.
// ---------------------------------------------------------------------------
template<bool EMIT>
__global__ __launch_bounds__(256)
void ln_k(const float* __restrict__ X, const float* __restrict__ g,
          const float* __restrict__ be, float* __restrict__ Y,
          bf16* __restrict__ Yh, bf16* __restrict__ Yl)
{
    const int r    = blockIdx.x * 8 + (threadIdx.x >> 5);
    const int lane = threadIdx.x & 31;
    const float* xr = X + (long long)r * D;

    float xv[8];
    float s = 0.f, ss = 0.f;
#pragma unroll
    for (int j = 0; j < 8; j++) {
        const float t = xr[lane + j * 32];
        xv[j] = t; s += t; ss += t * t;
    }
#pragma unroll
    for (int ofs = 16; ofs > 0; ofs >>= 1) {
        s  += __shfl_xor_sync(0xffffffffu, s,  ofs);
        ss += __shfl_xor_sync(0xffffffffu, ss, ofs);
    }
    const float mu  = s * (1.f / 256.f);
    const float var = ss * (1.f / 256.f) - mu * mu;
    const float rs  = rsqrtf(var + 1e-5f);

#pragma unroll
    for (int j = 0; j < 8; j++) {
        const int d = lane + j * 32;
        const float y = (xv[j] - mu) * rs * g[d] + be[d];
        Y[(long long)r * D + d] = y;
        if (EMIT) {
            bf16 h, l; split_bf16(y, h, l);
            Yh[(long long)r * D + d] = h;
            Yl[(long long)r * D + d] = l;
        }
    }
}

// ---------------------------------------------------------------------------
extern "C" void kernel_launch(void* const* d_in, const int* in_sizes, int n_in,
                              void* d_out, int out_size)
{
    const float* x   = (const float*)d_in[0];
    const float* Wq  = (const float*)d_in[1];
    const float* bq  = (const float*)d_in[2];
    const float* Wk  = (const float*)d_in[3];
    const float* bk  = (const float*)d_in[4];
    const float* Wv  = (const float*)d_in[5];
    const float* bv  = (const float*)d_in[6];
    const float* Wo  = (const float*)d_in[7];
    const float* bo  = (const float*)d_in[8];
    const float* W1  = (const float*)d_in[9];
    const float* b1  = (const float*)d_in[10];
    const float* W2  = (const float*)d_in[11];
    const float* b2  = (const float*)d_in[12];
    const float* g1  = (const float*)d_in[13];
    const float* be1 = (const float*)d_in[14];
    const float* g2  = (const float*)d_in[15];
    const float* be2 = (const float*)d_in[16];
    float* out = (float*)d_out;

    bf16 *xph, *xpl, *qh, *ql, *kh, *kl, *vh, *aoh, *aol, *hh, *hl, *ffh, *ffl;
    bf16 *wqh, *wql, *wkh, *wkl, *wvh, *wvl, *woh, *wol, *w1h, *w1l, *w2h, *w2l;
    float *sb, *hbuf;
    cudaGetSymbolAddress((void**)&xph, g_xph); cudaGetSymbolAddress((void**)&xpl, g_xpl);
    cudaGetSymbolAddress((void**)&qh,  g_qh);  cudaGetSymbolAddress((void**)&ql,  g_ql);
    cudaGetSymbolAddress((void**)&kh,  g_kh);  cudaGetSymbolAddress((void**)&kl,  g_kl);
    cudaGetSymbolAddress((void**)&vh,  g_vh);
    cudaGetSymbolAddress((void**)&aoh, g_aoh); cudaGetSymbolAddress((void**)&aol, g_aol);
    cudaGetSymbolAddress((void**)&sb,  g_s);   cudaGetSymbolAddress((void**)&hbuf, g_h);
    cudaGetSymbolAddress((void**)&hh,  g_hh);  cudaGetSymbolAddress((void**)&hl,  g_hl);
    cudaGetSymbolAddress((void**)&ffh, g_ffh); cudaGetSymbolAddress((void**)&ffl, g_ffl);
    cudaGetSymbolAddress((void**)&wqh, g_wqh); cudaGetSymbolAddress((void**)&wql, g_wql);
    cudaGetSymbolAddress((void**)&wkh, g_wkh); cudaGetSymbolAddress((void**)&wkl, g_wkl);
    cudaGetSymbolAddress((void**)&wvh, g_wvh); cudaGetSymbolAddress((void**)&wvl, g_wvl);
    cudaGetSymbolAddress((void**)&woh, g_woh); cudaGetSymbolAddress((void**)&wol, g_wol);
    cudaGetSymbolAddress((void**)&w1h, g_w1h); cudaGetSymbolAddress((void**)&w1l, g_w1l);
    cudaGetSymbolAddress((void**)&w2h, g_w2h); cudaGetSymbolAddress((void**)&w2l, g_w2l);

    cudaFuncSetAttribute(gemm_tc<true>,  cudaFuncAttributeMaxDynamicSharedMemorySize, GSMEM);
    cudaFuncSetAttribute(gemm_tc<false>, cudaFuncAttributeMaxDynamicSharedMemorySize, GSMEM);
    cudaFuncSetAttribute(attn_tc, cudaFuncAttributeMaxDynamicSharedMemorySize, ATT_SMEM);

    padcvt_x<<<(BN_ * SP * D) / 256, 256>>>(x, xph, xpl);
    wtall<<<1024, dim3(32, 8)>>>(Wq, Wk, Wv, Wo, W1, W2,
                                 wqh, wql, wkh, wkl, wvh, wvl,
                                 woh, wol, w1h, w1l, w2h, w2l);

    const float qscale = 0.17677669529663687f;   // 1/sqrt(32)

    // fused Q (z=0), K (z=1), V (z=2): conv GEMM over padded x
    {
        GCfg cq = { wqh, wql, bq, qscale, nullptr, qh, ql, 3, 3 * D, D, 3, 0 };
        GCfg ck = { wkh, wkl, bk, 1.f,    nullptr, kh, kl, 3, 3 * D, D, 3, 0 };
        GCfg cv = { wvh, wvl, bv, 1.f,    nullptr, vh, nullptr, 4, D, D, 1, 1 };
        gemm_tc<true><<<dim3(1, TOK / 128, 3), 512, GSMEM>>>(xph, xpl, D, nullptr, D, cq, ck, cv);
    }
    attn_tc<<<Bd * S1 * Hh, 256, ATT_SMEM>>>(qh, ql, kh, kl, vh, aoh, aol);
    {   // s = x + ao@Wo + bo
        GCfg co = { woh, wol, bo, 1.f, sb, nullptr, nullptr, 1, D, D, 1, 0 };
        gemm_tc<false><<<dim3(1, TOK / 128, 1), 512, GSMEM>>>(aoh, aol, D, x, D, co, co, co);
    }
    ln_k<true><<<TOK / 8, 256>>>(sb, g1, be1, hbuf, hh, hl);
    {   // ff = leaky(h@W1 + b1)
        GCfg c1c = { w1h, w1l, b1, 1.f, nullptr, ffh, ffl, 2, D, D, 1, 0 };
        gemm_tc<false><<<dim3(Fd / 256, TOK / 128, 1), 512, GSMEM>>>(hh, hl, D, nullptr, Fd, c1c, c1c, c1c);
    }
    {   // s = h + ff@W2 + b2
        GCfg c2c = { w2h, w2l, b2, 1.f, sb, nullptr, nullptr, 1, Fd, Fd, 1, 0 };
        gemm_tc<false><<<dim3(1, TOK / 128, 1), 512, GSMEM>>>(ffh, ffl, Fd, hbuf, D, c2c, c2c, c2c);
    }
    ln_k<false><<<TOK / 8, 256>>>(sb, g2, be2, out, nullptr, nullptr);
}

// round 8
// speedup vs baseline: 1.1830x; 1.1830x over previous
#include <cuda_runtime.h>
#include <cuda_bf16.h>
#include <cstdint>
#include <math.h>

using bf16 = __nv_bfloat16;

// ---------------- problem constants ----------------
constexpr int Bd  = 4;
constexpr int S1  = 64;
constexpr int S2  = 256;
constexpr int D   = 256;
constexpr int Hh  = 8;
constexpr int HD  = 32;
constexpr int Fd  = 1024;
constexpr int TOK = Bd * S1 * S2;     // 65536
constexpr int BN_ = Bd * S1;          // 256
constexpr int SP  = S2 + 2;           // padded time length 258

// ---------------- scratch (device globals) ----------------
__device__ bf16  g_xph[BN_ * SP * D];
__device__ bf16  g_xpl[BN_ * SP * D];
__device__ bf16  g_qh [TOK * D];
__device__ bf16  g_ql [TOK * D];
__device__ bf16  g_kh [TOK * D];
__device__ bf16  g_kl [TOK * D];
__device__ bf16  g_vh [TOK * D];
__device__ bf16  g_aoh[TOK * D];
__device__ bf16  g_aol[TOK * D];
__device__ float g_s  [TOK * D];
__device__ float g_h  [TOK * D];
__device__ bf16  g_hh [TOK * D];
__device__ bf16  g_hl [TOK * D];
__device__ bf16  g_ffh[TOK * Fd];
__device__ bf16  g_ffl[TOK * Fd];
// transposed weights, hi/lo
__device__ bf16 g_wqh[D * 3 * D], g_wql[D * 3 * D];
__device__ bf16 g_wkh[D * 3 * D], g_wkl[D * 3 * D];
__device__ bf16 g_wvh[D * D],     g_wvl[D * D];
__device__ bf16 g_woh[D * D],     g_wol[D * D];
__device__ bf16 g_w1h[Fd * D],    g_w1l[Fd * D];
__device__ bf16 g_w2h[D * Fd],    g_w2l[D * Fd];

// ---------------- helpers ----------------
__device__ __forceinline__ uint32_t smem_to_u32(const void* p) {
    uint32_t a;
    asm("{ .reg .u64 t; cvta.to.shared.u64 t, %1; cvt.u32.u64 %0, t; }" : "=r"(a) : "l"(p));
    return a;
}
#define CP_ASYNC16(s, g) \
    asm volatile("cp.async.cg.shared.global [%0], [%1], 16;" :: "r"((uint32_t)(s)), "l"(g))
#define CP_ASYNC_COMMIT() asm volatile("cp.async.commit_group;" ::: "memory")

__device__ __forceinline__ void ldsm4(uint32_t addr, uint32_t& r0, uint32_t& r1,
                                      uint32_t& r2, uint32_t& r3) {
    asm volatile("ldmatrix.sync.aligned.m8n8.x4.shared.b16 {%0,%1,%2,%3}, [%4];"
                 : "=r"(r0), "=r"(r1), "=r"(r2), "=r"(r3) : "r"(addr));
}
__device__ __forceinline__ void ldsm4t(uint32_t addr, uint32_t& r0, uint32_t& r1,
                                       uint32_t& r2, uint32_t& r3) {
    asm volatile("ldmatrix.sync.aligned.m8n8.x4.trans.shared.b16 {%0,%1,%2,%3}, [%4];"
                 : "=r"(r0), "=r"(r1), "=r"(r2), "=r"(r3) : "r"(addr));
}
__device__ __forceinline__ void mma_bf16(float* c, const uint32_t* a, const uint32_t* b) {
    asm volatile("mma.sync.aligned.m16n8k16.row.col.f32.bf16.bf16.f32 "
                 "{%0,%1,%2,%3}, {%4,%5,%6,%7}, {%8,%9}, {%0,%1,%2,%3};"
                 : "+f"(c[0]), "+f"(c[1]), "+f"(c[2]), "+f"(c[3])
                 : "r"(a[0]), "r"(a[1]), "r"(a[2]), "r"(a[3]), "r"(b[0]), "r"(b[1]));
}
__device__ __forceinline__ void split_bf16(float v, bf16& h, bf16& l) {
    h = __float2bfloat16(v);
    l = __float2bfloat16(v - __bfloat162float(h));
}
__device__ __forceinline__ uint32_t pack2(bf16 a, bf16 b) {
    __nv_bfloat162 p; p.x = a; p.y = b;
    return *(uint32_t*)&p;
}
// 64B-row swizzle: 4 16B columns, rotate by (row>>1)&3
__device__ __forceinline__ uint32_t sw64(int row, int c) {
    return (uint32_t)(row * 64 + ((c ^ ((row >> 1) & 3)) << 4));
}

// ---------------------------------------------------------------------------
// Tensor-core GEMM via mma.sync bf16, 128x128 block tile, BK=32, split-bf16
// (3 accumulating passes), cp.async 3-stage pipeline (single barrier per
// chunk), 2 CTAs/SM. gridDim.z == 2 -> blockIdx.z selects second set (Q/K).
// smem stage (32KB): [Ah 8K][Al 8K][Bh 8K][Bl 8K]
// EPI: 0 = bias*scl -> fp32 ; 1 = bias*scl + R -> fp32 ;
//      2 = bias*scl + leaky -> bf16 hi/lo ; 3 = bf16 hi/lo ; 4 = bf16 hi only
// ---------------------------------------------------------------------------
constexpr int GSTAGE = 32768;
constexpr int GSMEM  = 3 * GSTAGE;   // 98304

template<int EPI, bool CONV>
__global__ __launch_bounds__(256, 2)
void gemm_tc(const bf16* __restrict__ Ah, const bf16* __restrict__ Al, int ldA,
             const bf16* Bh_, const bf16* Bl_, int ldB,
             int Ktap, int ntaps, int tapbase, float scl_,
             const float* bias_, const float* __restrict__ R,
             float* Cf_, bf16* Ch_, bf16* Cl_, int Nt,
             const bf16* Bh2, const bf16* Bl2, const float* bias2, float scl2,
             bf16* Ch2, bf16* Cl2)
{
    extern __shared__ char smem[];
    const uint32_t sbase = smem_to_u32(smem);
    const int tid = threadIdx.x, wid = tid >> 5, lane = tid & 31;
    const int m0 = blockIdx.y * 128, n0 = blockIdx.x * 128;

    const bf16* Bh = Bh_;  const bf16* Bl = Bl_;
    const float* bias = bias_;  float scl = scl_;
    float* Cf = Cf_;  bf16* Ch = Ch_;  bf16* Cl = Cl_;
    if (blockIdx.z == 1) {
        Bh = Bh2; Bl = Bl2; bias = bias2; scl = scl2; Ch = Ch2; Cl = Cl2;
    }

    int rowbase;
    if (CONV) { const int bn = m0 >> 8; const int t0 = m0 & 255; rowbase = bn * SP + t0 + tapbase; }
    else      { rowbase = m0; }

    const int kcpt = Ktap >> 5;
    const int nch  = ntaps * kcpt;
    const int c4   = tid & 3;
    const int rw0  = tid >> 2;

    auto load_chunk = [&](int c, int stage) {
        const int tap = c / kcpt;
        const int kt  = (c - tap * kcpt) << 5;
        const size_t aoff = (size_t)(rowbase + tap) * ldA + kt + c4 * 8;
        const size_t boff = (size_t)n0 * ldB + (size_t)tap * Ktap + kt + c4 * 8;
        const uint32_t st = sbase + stage * GSTAGE;
#pragma unroll
        for (int i = 0; i < 2; i++) {
            const int row = rw0 + i * 64;
            const uint32_t so = sw64(row, c4);
            CP_ASYNC16(st +         so, Ah + aoff + (size_t)row * ldA);
            CP_ASYNC16(st +  8192 + so, Al + aoff + (size_t)row * ldA);
            CP_ASYNC16(st + 16384 + so, Bh + boff + (size_t)row * ldB);
            CP_ASYNC16(st + 24576 + so, Bl + boff + (size_t)row * ldB);
        }
        CP_ASYNC_COMMIT();
    };

    load_chunk(0, 0);
    load_chunk(1, 1);

    const int wm  = wid & 1,  wn  = wid >> 1;
    const int m0w = wm * 64,  n0w = wn * 32;
    const int tq  = lane >> 3, rin = lane & 7;
    const int aRow = m0w + (tq & 1) * 8 + rin;
    const int akh  = tq >> 1;
    const int bRow = n0w + (tq >> 1) * 8 + rin;
    const int bkh  = tq & 1;

    float acc[4][4][4];
#pragma unroll
    for (int i = 0; i < 4; i++)
#pragma unroll
        for (int j = 0; j < 4; j++)
#pragma unroll
            for (int r = 0; r < 4; r++) acc[i][j][r] = 0.f;

    for (int c = 0; c < nch; c++) {
        if (c + 1 < nch) asm volatile("cp.async.wait_group 1;" ::: "memory");
        else             asm volatile("cp.async.wait_group 0;" ::: "memory");
        __syncthreads();
        if (c + 2 < nch) load_chunk(c + 2, (c + 2) % 3);

        const uint32_t Ab = sbase + (c % 3) * GSTAGE;
        const uint32_t Bb = Ab + 16384;

#pragma unroll
        for (int ks = 0; ks < 2; ks++) {
            uint32_t ah[4][4], al[4][4], bh[4][2], bl[4][2];
#pragma unroll
            for (int mt = 0; mt < 4; mt++) {
                const int r = aRow + mt * 16;
                const uint32_t ad = Ab + sw64(r, ks * 2 + akh);
                ldsm4(ad,         ah[mt][0], ah[mt][1], ah[mt][2], ah[mt][3]);
                ldsm4(ad + 8192,  al[mt][0], al[mt][1], al[mt][2], al[mt][3]);
            }
#pragma unroll
            for (int nt2 = 0; nt2 < 2; nt2++) {
                const int r = bRow + nt2 * 16;
                const uint32_t bd = Bb + sw64(r, ks * 2 + bkh);
                uint32_t r0, r1, r2, r3;
                ldsm4(bd, r0, r1, r2, r3);
                bh[nt2 * 2][0] = r0; bh[nt2 * 2][1] = r1;
                bh[nt2 * 2 + 1][0] = r2; bh[nt2 * 2 + 1][1] = r3;
                ldsm4(bd + 8192, r0, r1, r2, r3);
                bl[nt2 * 2][0] = r0; bl[nt2 * 2][1] = r1;
                bl[nt2 * 2 + 1][0] = r2; bl[nt2 * 2 + 1][1] = r3;
            }
#pragma unroll
            for (int mt = 0; mt < 4; mt++)
#pragma unroll
                for (int nt = 0; nt < 4; nt++) {
                    mma_bf16(acc[mt][nt], ah[mt], bh[nt]);
                    mma_bf16(acc[mt][nt], ah[mt], bl[nt]);
                    mma_bf16(acc[mt][nt], al[mt], bh[nt]);
                }
        }
    }

    const int erow = lane >> 2;
    const int ecol = (lane & 3) * 2;
#pragma unroll
    for (int mt = 0; mt < 4; mt++) {
#pragma unroll
        for (int nt = 0; nt < 4; nt++) {
            const int col = n0 + n0w + nt * 8 + ecol;
            const float2 bi = *(const float2*)&bias[col];
#pragma unroll
            for (int half = 0; half < 2; half++) {
                const int row = m0 + m0w + mt * 16 + erow + half * 8;
                float v0 = (acc[mt][nt][half * 2 + 0] + bi.x) * scl;
                float v1 = (acc[mt][nt][half * 2 + 1] + bi.y) * scl;
                if (EPI == 1) {
                    const float2 rr = *(const float2*)&R[(size_t)row * Nt + col];
                    v0 += rr.x; v1 += rr.y;
                }
                if (EPI >= 2) {
                    if (EPI == 2) {
                        v0 = v0 > 0.f ? v0 : 0.01f * v0;
                        v1 = v1 > 0.f ? v1 : 0.01f * v1;
                    }
                    bf16 h0, l0, h1, l1;
                    split_bf16(v0, h0, l0); split_bf16(v1, h1, l1);
                    *(uint32_t*)&Ch[(size_t)row * Nt + col] = pack2(h0, h1);
                    if (EPI != 4)
                        *(uint32_t*)&Cl[(size_t)row * Nt + col] = pack2(l0, l1);
                } else {
                    float2 o; o.x = v0; o.y = v1;
                    *(float2*)&Cf[(size_t)row * Nt + col] = o;
                }
            }
        }
    }
}

// ---------------------------------------------------------------------------
// pad + split x into bf16 hi/lo padded buffer [bn][258][256]
// ---------------------------------------------------------------------------
__global__ __launch_bounds__(256)
void padcvt_x(const float* __restrict__ x, bf16* __restrict__ xh, bf16* __restrict__ xl)
{
    const size_t i = (size_t)blockIdx.x * 256 + threadIdx.x;
    const int d = (int)(i & 255);
    const size_t rest = i >> 8;
    const int t = (int)(rest % SP);
    const size_t bn = rest / SP;
    float v = 0.f;
    if (t >= 1 && t <= S2) v = x[(bn * S2 + (t - 1)) * D + d];
    bf16 h, l; split_bf16(v, h, l);
    xh[i] = h; xl[i] = l;
}

// ---------------------------------------------------------------------------
// fused weight transpose+split: 6 weights in one launch (1024 32x32 tiles)
// ---------------------------------------------------------------------------
__global__ __launch_bounds__(256)
void wtall(const float* __restrict__ Wq, const float* __restrict__ Wk,
           const float* __restrict__ Wv, const float* __restrict__ Wo,
           const float* __restrict__ W1, const float* __restrict__ W2,
           bf16* wqh, bf16* wql, bf16* wkh, bf16* wkl,
           bf16* wvh, bf16* wvl, bf16* woh, bf16* wol,
           bf16* w1h, bf16* w1l, bf16* w2h, bf16* w2l)
{
    __shared__ float ts[32][33];
    const int t = blockIdx.x;
    const float* W; bf16 *Bh, *Bl; int K, N, lt;
    if      (t < 192) { W = Wq; Bh = wqh; Bl = wql; K = 768;  N = 256;  lt = t; }
    else if (t < 384) { W = Wk; Bh = wkh; Bl = wkl; K = 768;  N = 256;  lt = t - 192; }
    else if (t < 448) { W = Wv; Bh = wvh; Bl = wvl; K = 256;  N = 256;  lt = t - 384; }
    else if (t < 512) { W = Wo; Bh = woh; Bl = wol; K = 256;  N = 256;  lt = t - 448; }
    else if (t < 768) { W = W1; Bh = w1h; Bl = w1l; K = 256;  N = 1024; lt = t - 512; }
    else              { W = W2; Bh = w2h; Bl = w2l; K = 1024; N = 256;  lt = t - 768; }
    const int ntn = N / 32;
    const int n0 = (lt % ntn) * 32, k0 = (lt / ntn) * 32;
    const int tx = threadIdx.x, ty = threadIdx.y;   // 32 x 8
#pragma unroll
    for (int j = 0; j < 4; j++)
        ts[ty + j * 8][tx] = W[(size_t)(k0 + ty + j * 8) * N + n0 + tx];
    __syncthreads();
#pragma unroll
    for (int j = 0; j < 4; j++) {
        const float v = ts[tx][ty + j * 8];
        bf16 h, l; split_bf16(v, h, l);
        const size_t o = (size_t)(n0 + ty + j * 8) * K + k0 + tx;
        Bh[o] = h; Bl[o] = l;
    }
}

// ---------------------------------------------------------------------------
// Flash attention on tensor cores. One block per (b,n,h); 8 warps x 32 rows.
// QK scores: 3-pass split-bf16. PV: single-pass bf16; V B-frags come from
// row-major V smem via ldmatrix.x4.trans (no transpose copy, no V-lo).
// smem: Qh Ql Kh Kl Vh, 5 x 20480 (rows stride 80B -> conflict-free)
// ---------------------------------------------------------------------------
constexpr int ATT_SMEM = 5 * 20480;   // 102400

__global__ __launch_bounds__(256, 2)
void attn_tc(const bf16* __restrict__ qh, const bf16* __restrict__ ql,
             const bf16* __restrict__ kh, const bf16* __restrict__ kl,
             const bf16* __restrict__ vh,
             bf16* __restrict__ oh, bf16* __restrict__ ol)
{
    extern __shared__ char smem[];
    const uint32_t sb = smem_to_u32(smem);
    const uint32_t Qh = sb, Ql_ = sb + 20480, Kh = sb + 40960, Kl_ = sb + 61440;
    const uint32_t Vh = sb + 81920;

    const int tid = threadIdx.x, wid = tid >> 5, lane = tid & 31;
    const int h = blockIdx.x & 7, bn = blockIdx.x >> 3;
    const size_t gbase = (size_t)bn * 256 * 256 + h * 32;

    for (int idx = tid; idx < 1024; idx += 256) {
        const int row = idx >> 2, c = idx & 3;
        const size_t g = gbase + (size_t)row * 256 + c * 8;
        const uint32_t so = row * 80 + c * 16;
        CP_ASYNC16(Qh  + so, qh + g);
        CP_ASYNC16(Ql_ + so, ql + g);
        CP_ASYNC16(Kh  + so, kh + g);
        CP_ASYNC16(Kl_ + so, kl + g);
        CP_ASYNC16(Vh  + so, vh + g);
    }
    CP_ASYNC_COMMIT();
    asm volatile("cp.async.wait_group 0;" ::: "memory");
    __syncthreads();

    const int tq = lane >> 3, rin = lane & 7;
    const int aR  = (tq & 1) * 8 + rin;
    const int akh = tq >> 1;
    const int bR  = (tq >> 1) * 8 + rin;
    const int bkh = tq & 1;
    const int vrow  = (lane & 7) + ((lane >> 3) & 1) * 8;
    const int vcolb = ((lane >> 4) & 1) * 16;

    uint32_t qfh[2][2][4], qfl[2][2][4];
#pragma unroll
    for (int mt = 0; mt < 2; mt++)
#pragma unroll
        for (int ks = 0; ks < 2; ks++) {
            const uint32_t ad = Qh + (uint32_t)((wid * 32 + mt * 16 + aR) * 80)
                              + (uint32_t)((ks * 2 + akh) * 16);
            ldsm4(ad,          qfh[mt][ks][0], qfh[mt][ks][1], qfh[mt][ks][2], qfh[mt][ks][3]);
            ldsm4(ad + 20480,  qfl[mt][ks][0], qfl[mt][ks][1], qfl[mt][ks][2], qfl[mt][ks][3]);
        }

    float O[2][4][4];
#pragma unroll
    for (int mt = 0; mt < 2; mt++)
#pragma unroll
        for (int j = 0; j < 4; j++)
#pragma unroll
            for (int r = 0; r < 4; r++) O[mt][j][r] = 0.f;
    float mrow[2][2] = { {-1e30f, -1e30f}, {-1e30f, -1e30f} };
    float lrow[2][2] = { {0.f, 0.f}, {0.f, 0.f} };

    for (int s0 = 0; s0 < 256; s0 += 64) {
        float acc[2][8][4];
#pragma unroll
        for (int mt = 0; mt < 2; mt++)
#pragma unroll
            for (int j = 0; j < 8; j++)
#pragma unroll
                for (int r = 0; r < 4; r++) acc[mt][j][r] = 0.f;

#pragma unroll
        for (int ks = 0; ks < 2; ks++) {
            uint32_t kbh[8][2], kbl[8][2];
#pragma unroll
            for (int g = 0; g < 4; g++) {
                const uint32_t kd = Kh + (uint32_t)((s0 + g * 16 + bR) * 80)
                                  + (uint32_t)((ks * 2 + bkh) * 16);
                uint32_t r0, r1, r2, r3;
                ldsm4(kd, r0, r1, r2, r3);
                kbh[g * 2][0] = r0; kbh[g * 2][1] = r1;
                kbh[g * 2 + 1][0] = r2; kbh[g * 2 + 1][1] = r3;
                ldsm4(kd + 20480, r0, r1, r2, r3);
                kbl[g * 2][0] = r0; kbl[g * 2][1] = r1;
                kbl[g * 2 + 1][0] = r2; kbl[g * 2 + 1][1] = r3;
            }
#pragma unroll
            for (int mt = 0; mt < 2; mt++)
#pragma unroll
                for (int j = 0; j < 8; j++) {
                    mma_bf16(acc[mt][j], qfh[mt][ks], kbh[j]);
                    mma_bf16(acc[mt][j], qfh[mt][ks], kbl[j]);
                    mma_bf16(acc[mt][j], qfl[mt][ks], kbh[j]);
                }
        }

#pragma unroll
        for (int mt = 0; mt < 2; mt++) {
            float mxA = -1e30f, mxB = -1e30f;
#pragma unroll
            for (int j = 0; j < 8; j++) {
                mxA = fmaxf(mxA, fmaxf(acc[mt][j][0], acc[mt][j][1]));
                mxB = fmaxf(mxB, fmaxf(acc[mt][j][2], acc[mt][j][3]));
            }
            mxA = fmaxf(mxA, __shfl_xor_sync(0xffffffffu, mxA, 1));
            mxA = fmaxf(mxA, __shfl_xor_sync(0xffffffffu, mxA, 2));
            mxB = fmaxf(mxB, __shfl_xor_sync(0xffffffffu, mxB, 1));
            mxB = fmaxf(mxB, __shfl_xor_sync(0xffffffffu, mxB, 2));
            const float mnA = fmaxf(mrow[mt][0], mxA);
            const float mnB = fmaxf(mrow[mt][1], mxB);
            const float fA = __expf(mrow[mt][0] - mnA);
            const float fB = __expf(mrow[mt][1] - mnB);
            mrow[mt][0] = mnA; mrow[mt][1] = mnB;
            float sA = 0.f, sB = 0.f;
#pragma unroll
            for (int j = 0; j < 8; j++) {
                acc[mt][j][0] = __expf(acc[mt][j][0] - mnA);
                acc[mt][j][1] = __expf(acc[mt][j][1] - mnA);
                acc[mt][j][2] = __expf(acc[mt][j][2] - mnB);
                acc[mt][j][3] = __expf(acc[mt][j][3] - mnB);
                sA += acc[mt][j][0] + acc[mt][j][1];
                sB += acc[mt][j][2] + acc[mt][j][3];
            }
            lrow[mt][0] = lrow[mt][0] * fA + sA;
            lrow[mt][1] = lrow[mt][1] * fB + sB;
#pragma unroll
            for (int j = 0; j < 4; j++) {
                O[mt][j][0] *= fA; O[mt][j][1] *= fA;
                O[mt][j][2] *= fB; O[mt][j][3] *= fB;
            }
        }

#pragma unroll
        for (int kt = 0; kt < 4; kt++) {
            uint32_t vb[4][2];
#pragma unroll
            for (int nb = 0; nb < 2; nb++) {
                const uint32_t vd = Vh + (uint32_t)((s0 + kt * 16 + vrow) * 80)
                                  + (uint32_t)(nb * 32 + vcolb);
                uint32_t r0, r1, r2, r3;
                ldsm4t(vd, r0, r1, r2, r3);
                vb[nb * 2][0] = r0; vb[nb * 2][1] = r1;
                vb[nb * 2 + 1][0] = r2; vb[nb * 2 + 1][1] = r3;
            }
#pragma unroll
            for (int mt = 0; mt < 2; mt++) {
                uint32_t ph[4];
#pragma unroll
                for (int half = 0; half < 2; half++) {
                    const int j = 2 * kt + half;
                    ph[half * 2 + 0] = pack2(__float2bfloat16(acc[mt][j][0]),
                                             __float2bfloat16(acc[mt][j][1]));
                    ph[half * 2 + 1] = pack2(__float2bfloat16(acc[mt][j][2]),
                                             __float2bfloat16(acc[mt][j][3]));
                }
#pragma unroll
                for (int j2 = 0; j2 < 4; j2++)
                    mma_bf16(O[mt][j2], ph, vb[j2]);
            }
        }
    }

#pragma unroll
    for (int mt = 0; mt < 2; mt++) {
        float lA = lrow[mt][0], lB = lrow[mt][1];
        lA += __shfl_xor_sync(0xffffffffu, lA, 1);
        lA += __shfl_xor_sync(0xffffffffu, lA, 2);
        lB += __shfl_xor_sync(0xffffffffu, lB, 1);
        lB += __shfl_xor_sync(0xffffffffu, lB, 2);
        const float invA = 1.f / lA, invB = 1.f / lB;
        const int rowA = wid * 32 + mt * 16 + (lane >> 2);
        const size_t gA = gbase + (size_t)rowA * 256;
        const size_t gB = gA + (size_t)8 * 256;
#pragma unroll
        for (int j2 = 0; j2 < 4; j2++) {
            const int col = j2 * 8 + (lane & 3) * 2;
            const float a0 = O[mt][j2][0] * invA, a1 = O[mt][j2][1] * invA;
            const float b0 = O[mt][j2][2] * invB, b1 = O[mt][j2][3] * invB;
            bf16 h0, l0, h1, l1;
            split_bf16(a0, h0, l0); split_bf16(a1, h1, l1);
            *(uint32_t*)&oh[gA + col] = pack2(h0, h1);
            *(uint32_t*)&ol[gA + col] = pack2(l0, l1);
            split_bf16(b0, h0, l0); split_bf16(b1, h1, l1);
            *(uint32_t*)&oh[gB + col] = pack2(h0, h1);
            *(uint32_t*)&ol[gB + col] = pack2(l0, l1);
        }
    }
}

// ---------------------------------------------------------------------------
// LayerNorm (D=256). Optionally emits bf16 hi/lo of the normalized output.
// ---------------------------------------------------------------------------
template<bool EMIT>
__global__ __launch_bounds__(256)
void ln_k(const float* __restrict__ X, const float* __restrict__ g,
          const float* __restrict__ be, float* __restrict__ Y,
          bf16* __restrict__ Yh, bf16* __restrict__ Yl)
{
    const int r    = blockIdx.x * 8 + (threadIdx.x >> 5);
    const int lane = threadIdx.x & 31;
    const float* xr = X + (long long)r * D;

    float xv[8];
    float s = 0.f, ss = 0.f;
#pragma unroll
    for (int j = 0; j < 8; j++) {
        const float t = xr[lane + j * 32];
        xv[j] = t; s += t; ss += t * t;
    }
#pragma unroll
    for (int ofs = 16; ofs > 0; ofs >>= 1) {
        s  += __shfl_xor_sync(0xffffffffu, s,  ofs);
        ss += __shfl_xor_sync(0xffffffffu, ss, ofs);
    }
    const float mu  = s * (1.f / 256.f);
    const float var = ss * (1.f / 256.f) - mu * mu;
    const float rs  = rsqrtf(var + 1e-5f);

#pragma unroll
    for (int j = 0; j < 8; j++) {
        const int d = lane + j * 32;
        const float y = (xv[j] - mu) * rs * g[d] + be[d];
        Y[(long long)r * D + d] = y;
        if (EMIT) {
            bf16 h, l; split_bf16(y, h, l);
            Yh[(long long)r * D + d] = h;
            Yl[(long long)r * D + d] = l;
        }
    }
}

// ---------------------------------------------------------------------------
extern "C" void kernel_launch(void* const* d_in, const int* in_sizes, int n_in,
                              void* d_out, int out_size)
{
    const float* x   = (const float*)d_in[0];
    const float* Wq  = (const float*)d_in[1];
    const float* bq  = (const float*)d_in[2];
    const float* Wk  = (const float*)d_in[3];
    const float* bk  = (const float*)d_in[4];
    const float* Wv  = (const float*)d_in[5];
    const float* bv  = (const float*)d_in[6];
    const float* Wo  = (const float*)d_in[7];
    const float* bo  = (const float*)d_in[8];
    const float* W1  = (const float*)d_in[9];
    const float* b1  = (const float*)d_in[10];
    const float* W2  = (const float*)d_in[11];
    const float* b2  = (const float*)d_in[12];
    const float* g1  = (const float*)d_in[13];
    const float* be1 = (const float*)d_in[14];
    const float* g2  = (const float*)d_in[15];
    const float* be2 = (const float*)d_in[16];
    float* out = (float*)d_out;

    bf16 *xph, *xpl, *qh, *ql, *kh, *kl, *vh, *aoh, *aol, *hh, *hl, *ffh, *ffl;
    bf16 *wqh, *wql, *wkh, *wkl, *wvh, *wvl, *woh, *wol, *w1h, *w1l, *w2h, *w2l;
    float *sb, *hbuf;
    cudaGetSymbolAddress((void**)&xph, g_xph); cudaGetSymbolAddress((void**)&xpl, g_xpl);
    cudaGetSymbolAddress((void**)&qh,  g_qh);  cudaGetSymbolAddress((void**)&ql,  g_ql);
    cudaGetSymbolAddress((void**)&kh,  g_kh);  cudaGetSymbolAddress((void**)&kl,  g_kl);
    cudaGetSymbolAddress((void**)&vh,  g_vh);
    cudaGetSymbolAddress((void**)&aoh, g_aoh); cudaGetSymbolAddress((void**)&aol, g_aol);
    cudaGetSymbolAddress((void**)&sb,  g_s);   cudaGetSymbolAddress((void**)&hbuf, g_h);
    cudaGetSymbolAddress((void**)&hh,  g_hh);  cudaGetSymbolAddress((void**)&hl,  g_hl);
    cudaGetSymbolAddress((void**)&ffh, g_ffh); cudaGetSymbolAddress((void**)&ffl, g_ffl);
    cudaGetSymbolAddress((void**)&wqh, g_wqh); cudaGetSymbolAddress((void**)&wql, g_wql);
    cudaGetSymbolAddress((void**)&wkh, g_wkh); cudaGetSymbolAddress((void**)&wkl, g_wkl);
    cudaGetSymbolAddress((void**)&wvh, g_wvh); cudaGetSymbolAddress((void**)&wvl, g_wvl);
    cudaGetSymbolAddress((void**)&woh, g_woh); cudaGetSymbolAddress((void**)&wol, g_wol);
    cudaGetSymbolAddress((void**)&w1h, g_w1h); cudaGetSymbolAddress((void**)&w1l, g_w1l);
    cudaGetSymbolAddress((void**)&w2h, g_w2h); cudaGetSymbolAddress((void**)&w2l, g_w2l);

    cudaFuncSetAttribute(gemm_tc<3, true>,  cudaFuncAttributeMaxDynamicSharedMemorySize, GSMEM);
    cudaFuncSetAttribute(gemm_tc<4, true>,  cudaFuncAttributeMaxDynamicSharedMemorySize, GSMEM);
    cudaFuncSetAttribute(gemm_tc<1, false>, cudaFuncAttributeMaxDynamicSharedMemorySize, GSMEM);
    cudaFuncSetAttribute(gemm_tc<2, false>, cudaFuncAttributeMaxDynamicSharedMemorySize, GSMEM);
    cudaFuncSetAttribute(attn_tc, cudaFuncAttributeMaxDynamicSharedMemorySize, ATT_SMEM);

    padcvt_x<<<(BN_ * SP * D) / 256, 256>>>(x, xph, xpl);
    wtall<<<1024, dim3(32, 8)>>>(Wq, Wk, Wv, Wo, W1, W2,
                                 wqh, wql, wkh, wkl, wvh, wvl,
                                 woh, wol, w1h, w1l, w2h, w2l);

    const dim3 gQK(D / 128, TOK / 128, 2);   // fused Q (z=0) + K (z=1)
    const dim3 gD (D / 128, TOK / 128);
    const dim3 gF (Fd / 128, TOK / 128);
    const float qscale = 0.17677669529663687f;   // 1/sqrt(32)

    // fused Q+K (3-tap conv; bf16 hi/lo out; Q pre-scaled)
    gemm_tc<3, true><<<gQK, 256, GSMEM>>>(xph, xpl, D, wqh, wql, 3 * D, D, 3, 0, qscale,
                                          bq, nullptr, nullptr, qh, ql, D,
                                          wkh, wkl, bk, 1.f, kh, kl);
    // V (bf16 hi only)
    gemm_tc<4, true><<<gD, 256, GSMEM>>>(xph, xpl, D, wvh, wvl, D, D, 1, 1, 1.f,
                                         bv, nullptr, nullptr, vh, nullptr, D,
                                         nullptr, nullptr, nullptr, 0.f, nullptr, nullptr);
    attn_tc<<<Bd * S1 * Hh, 256, ATT_SMEM>>>(qh, ql, kh, kl, vh, aoh, aol);
    gemm_tc<1, false><<<gD, 256, GSMEM>>>(aoh, aol, D, woh, wol, D, D, 1, 0, 1.f,
                                          bo, x, sb, nullptr, nullptr, D,
                                          nullptr, nullptr, nullptr, 0.f, nullptr, nullptr);
    ln_k<true><<<TOK / 8, 256>>>(sb, g1, be1, hbuf, hh, hl);
    gemm_tc<2, false><<<gF, 256, GSMEM>>>(hh, hl, D, w1h, w1l, D, D, 1, 0, 1.f,
                                          b1, nullptr, nullptr, ffh, ffl, Fd,
                                          nullptr, nullptr, nullptr, 0.f, nullptr, nullptr);
    gemm_tc<1, false><<<gD, 256, GSMEM>>>(ffh, ffl, Fd, w2h, w2l, Fd, Fd, 1, 0, 1.f,
                                          b2, hbuf, sb, nullptr, nullptr, D,
                                          nullptr, nullptr, nullptr, 0.f, nullptr, nullptr);
    ln_k<false><<<TOK / 8, 256>>>(sb, g2, be2, out, nullptr, nullptr);
}

// round 10
// speedup vs baseline: 2.0128x; 1.7015x over previous
#include <cuda_runtime.h>
#include <cuda_bf16.h>
#include <cstdint>
#include <math.h>

using bf16 = __nv_bfloat16;

// ---------------- problem constants ----------------
constexpr int Bd  = 4;
constexpr int S1  = 64;
constexpr int S2  = 256;
constexpr int D   = 256;
constexpr int Hh  = 8;
constexpr int HD  = 32;
constexpr int Fd  = 1024;
constexpr int TOK = Bd * S1 * S2;     // 65536
constexpr int BN_ = Bd * S1;          // 256
constexpr int SP  = S2 + 2;           // padded time length 258

// ---------------- scratch (device globals) ----------------
__device__ bf16  g_xph[BN_ * SP * D];
__device__ bf16  g_xpl[BN_ * SP * D];
__device__ bf16  g_qh [TOK * D];
__device__ bf16  g_kh [TOK * D];
__device__ bf16  g_vh [TOK * D];
__device__ bf16  g_aoh[TOK * D];
__device__ float g_s  [TOK * D];
__device__ float g_h  [TOK * D];
__device__ bf16  g_hh [TOK * D];
__device__ bf16  g_ffh[TOK * Fd];
// transposed weights (hi only)
__device__ bf16 g_wqh[D * 3 * D];
__device__ bf16 g_wkh[D * 3 * D];
__device__ bf16 g_wvh[D * D];
__device__ bf16 g_woh[D * D];
__device__ bf16 g_w1h[Fd * D];
__device__ bf16 g_w2h[D * Fd];

// ---------------- helpers ----------------
__device__ __forceinline__ uint32_t smem_to_u32(const void* p) {
    uint32_t a;
    asm("{ .reg .u64 t; cvta.to.shared.u64 t, %1; cvt.u32.u64 %0, t; }" : "=r"(a) : "l"(p));
    return a;
}
#define CP_ASYNC16(s, g) \
    asm volatile("cp.async.cg.shared.global [%0], [%1], 16;" :: "r"((uint32_t)(s)), "l"(g))
#define CP_ASYNC_COMMIT() asm volatile("cp.async.commit_group;" ::: "memory")

__device__ __forceinline__ void ldsm4(uint32_t addr, uint32_t& r0, uint32_t& r1,
                                      uint32_t& r2, uint32_t& r3) {
    asm volatile("ldmatrix.sync.aligned.m8n8.x4.shared.b16 {%0,%1,%2,%3}, [%4];"
                 : "=r"(r0), "=r"(r1), "=r"(r2), "=r"(r3) : "r"(addr));
}
__device__ __forceinline__ void ldsm4t(uint32_t addr, uint32_t& r0, uint32_t& r1,
                                       uint32_t& r2, uint32_t& r3) {
    asm volatile("ldmatrix.sync.aligned.m8n8.x4.trans.shared.b16 {%0,%1,%2,%3}, [%4];"
                 : "=r"(r0), "=r"(r1), "=r"(r2), "=r"(r3) : "r"(addr));
}
__device__ __forceinline__ void mma_bf16(float* c, const uint32_t* a, const uint32_t* b) {
    asm volatile("mma.sync.aligned.m16n8k16.row.col.f32.bf16.bf16.f32 "
                 "{%0,%1,%2,%3}, {%4,%5,%6,%7}, {%8,%9}, {%0,%1,%2,%3};"
                 : "+f"(c[0]), "+f"(c[1]), "+f"(c[2]), "+f"(c[3])
                 : "r"(a[0]), "r"(a[1]), "r"(a[2]), "r"(a[3]), "r"(b[0]), "r"(b[1]));
}
__device__ __forceinline__ void split_bf16(float v, bf16& h, bf16& l) {
    h = __float2bfloat16(v);
    l = __float2bfloat16(v - __bfloat162float(h));
}
__device__ __forceinline__ uint32_t pack2(bf16 a, bf16 b) {
    __nv_bfloat162 p; p.x = a; p.y = b;
    return *(uint32_t*)&p;
}
// 64B-row swizzle: 4 16B columns, rotate by (row>>1)&3
__device__ __forceinline__ uint32_t sw64(int row, int c) {
    return (uint32_t)(row * 64 + ((c ^ ((row >> 1) & 3)) << 4));
}

// ---------------------------------------------------------------------------
// Tensor-core GEMM via mma.sync bf16, 128x128 block tile, BK=32, NPASS
// accumulating passes (2: Ah*Bh + Al*Bh ; 1: Ah*Bh), 3-stage cp.async
// pipeline, 2 CTAs/SM. gridDim.z == 2 -> blockIdx.z picks second set (Q/K).
// stage: [Ah 8K][Al 8K if NPASS==2][Bh 8K]
// EPI: 1 = bias*scl + R -> fp32 ; 2 = bias*scl + leaky -> bf16 hi ;
//      4 = bias*scl -> bf16 hi
// ---------------------------------------------------------------------------
template<int EPI, bool CONV, int NPASS>
__global__ __launch_bounds__(256, 2)
void gemm_tc(const bf16* __restrict__ Ah, const bf16* __restrict__ Al, int ldA,
             const bf16* Bh_, int ldB,
             int Ktap, int ntaps, int tapbase, float scl_,
             const float* bias_, const float* __restrict__ R,
             float* __restrict__ Cf, bf16* Ch_, int Nt,
             const bf16* Bh2, const float* bias2, float scl2, bf16* Ch2)
{
    constexpr int STAGE  = (NPASS == 2) ? 24576 : 16384;
    constexpr int BH_OFF = (NPASS == 2) ? 16384 : 8192;

    extern __shared__ char smem[];
    const uint32_t sbase = smem_to_u32(smem);
    const int tid = threadIdx.x, wid = tid >> 5, lane = tid & 31;
    const int m0 = blockIdx.y * 128, n0 = blockIdx.x * 128;

    const bf16* Bh = Bh_;
    const float* bias = bias_;  float scl = scl_;
    bf16* Ch = Ch_;
    if (blockIdx.z == 1) { Bh = Bh2; bias = bias2; scl = scl2; Ch = Ch2; }

    int rowbase;
    if (CONV) { const int bn = m0 >> 8; const int t0 = m0 & 255; rowbase = bn * SP + t0 + tapbase; }
    else      { rowbase = m0; }

    const int kcpt = Ktap >> 5;
    const int nch  = ntaps * kcpt;
    const int c4   = tid & 3;
    const int rw0  = tid >> 2;

    auto load_chunk = [&](int c, int stage) {
        const int tap = c / kcpt;
        const int kt  = (c - tap * kcpt) << 5;
        const size_t aoff = (size_t)(rowbase + tap) * ldA + kt + c4 * 8;
        const size_t boff = (size_t)n0 * ldB + (size_t)tap * Ktap + kt + c4 * 8;
        const uint32_t st = sbase + stage * STAGE;
#pragma unroll
        for (int i = 0; i < 2; i++) {
            const int row = rw0 + i * 64;
            const uint32_t so = sw64(row, c4);
            CP_ASYNC16(st + so, Ah + aoff + (size_t)row * ldA);
            if (NPASS == 2)
                CP_ASYNC16(st + 8192 + so, Al + aoff + (size_t)row * ldA);
            CP_ASYNC16(st + BH_OFF + so, Bh + boff + (size_t)row * ldB);
        }
        CP_ASYNC_COMMIT();
    };

    load_chunk(0, 0);
    load_chunk(1, 1);

    const int wm  = wid & 1,  wn  = wid >> 1;
    const int m0w = wm * 64,  n0w = wn * 32;
    const int tq  = lane >> 3, rin = lane & 7;
    const int aRow = m0w + (tq & 1) * 8 + rin;
    const int akh  = tq >> 1;
    const int bRow = n0w + (tq >> 1) * 8 + rin;
    const int bkh  = tq & 1;

    float acc[4][4][4];
#pragma unroll
    for (int i = 0; i < 4; i++)
#pragma unroll
        for (int j = 0; j < 4; j++)
#pragma unroll
            for (int r = 0; r < 4; r++) acc[i][j][r] = 0.f;

    for (int c = 0; c < nch; c++) {
        if (c + 1 < nch) asm volatile("cp.async.wait_group 1;" ::: "memory");
        else             asm volatile("cp.async.wait_group 0;" ::: "memory");
        __syncthreads();
        if (c + 2 < nch) load_chunk(c + 2, (c + 2) % 3);

        const uint32_t Ab = sbase + (c % 3) * STAGE;
        const uint32_t Bb = Ab + BH_OFF;

#pragma unroll
        for (int ks = 0; ks < 2; ks++) {
            uint32_t ah[4][4], al[4][4], bh[4][2];
#pragma unroll
            for (int mt = 0; mt < 4; mt++) {
                const int r = aRow + mt * 16;
                const uint32_t ad = Ab + sw64(r, ks * 2 + akh);
                ldsm4(ad, ah[mt][0], ah[mt][1], ah[mt][2], ah[mt][3]);
                if (NPASS == 2)
                    ldsm4(ad + 8192, al[mt][0], al[mt][1], al[mt][2], al[mt][3]);
            }
#pragma unroll
            for (int nt2 = 0; nt2 < 2; nt2++) {
                const int r = bRow + nt2 * 16;
                const uint32_t bd = Bb + sw64(r, ks * 2 + bkh);
                uint32_t r0, r1, r2, r3;
                ldsm4(bd, r0, r1, r2, r3);
                bh[nt2 * 2][0] = r0; bh[nt2 * 2][1] = r1;
                bh[nt2 * 2 + 1][0] = r2; bh[nt2 * 2 + 1][1] = r3;
            }
#pragma unroll
            for (int mt = 0; mt < 4; mt++)
#pragma unroll
                for (int nt = 0; nt < 4; nt++) {
                    mma_bf16(acc[mt][nt], ah[mt], bh[nt]);
                    if (NPASS == 2)
                        mma_bf16(acc[mt][nt], al[mt], bh[nt]);
                }
        }
    }

    const int erow = lane >> 2;
    const int ecol = (lane & 3) * 2;
#pragma unroll
    for (int mt = 0; mt < 4; mt++) {
#pragma unroll
        for (int nt = 0; nt < 4; nt++) {
            const int col = n0 + n0w + nt * 8 + ecol;
            const float2 bi = *(const float2*)&bias[col];
#pragma unroll
            for (int half = 0; half < 2; half++) {
                const int row = m0 + m0w + mt * 16 + erow + half * 8;
                float v0 = (acc[mt][nt][half * 2 + 0] + bi.x) * scl;
                float v1 = (acc[mt][nt][half * 2 + 1] + bi.y) * scl;
                if (EPI == 1) {
                    const float2 rr = *(const float2*)&R[(size_t)row * Nt + col];
                    v0 += rr.x; v1 += rr.y;
                    float2 o; o.x = v0; o.y = v1;
                    *(float2*)&Cf[(size_t)row * Nt + col] = o;
                } else {
                    if (EPI == 2) {
                        v0 = v0 > 0.f ? v0 : 0.01f * v0;
                        v1 = v1 > 0.f ? v1 : 0.01f * v1;
                    }
                    *(uint32_t*)&Ch[(size_t)row * Nt + col] =
                        pack2(__float2bfloat16(v0), __float2bfloat16(v1));
                }
            }
        }
    }
}

// ---------------------------------------------------------------------------
// pad + split x into bf16 hi/lo padded buffer [bn][258][256]
// ---------------------------------------------------------------------------
__global__ __launch_bounds__(256)
void padcvt_x(const float* __restrict__ x, bf16* __restrict__ xh, bf16* __restrict__ xl)
{
    const size_t i = (size_t)blockIdx.x * 256 + threadIdx.x;
    const int d = (int)(i & 255);
    const size_t rest = i >> 8;
    const int t = (int)(rest % SP);
    const size_t bn = rest / SP;
    float v = 0.f;
    if (t >= 1 && t <= S2) v = x[(bn * S2 + (t - 1)) * D + d];
    bf16 h, l; split_bf16(v, h, l);
    xh[i] = h; xl[i] = l;
}

// ---------------------------------------------------------------------------
// fused weight transpose+convert (hi only): 6 weights in one launch
// ---------------------------------------------------------------------------
__global__ __launch_bounds__(256)
void wtall(const float* __restrict__ Wq, const float* __restrict__ Wk,
           const float* __restrict__ Wv, const float* __restrict__ Wo,
           const float* __restrict__ W1, const float* __restrict__ W2,
           bf16* wqh, bf16* wkh, bf16* wvh, bf16* woh, bf16* w1h, bf16* w2h)
{
    __shared__ float ts[32][33];
    const int t = blockIdx.x;
    const float* W; bf16* Bh; int K, N, lt;
    if      (t < 192) { W = Wq; Bh = wqh; K = 768;  N = 256;  lt = t; }
    else if (t < 384) { W = Wk; Bh = wkh; K = 768;  N = 256;  lt = t - 192; }
    else if (t < 448) { W = Wv; Bh = wvh; K = 256;  N = 256;  lt = t - 384; }
    else if (t < 512) { W = Wo; Bh = woh; K = 256;  N = 256;  lt = t - 448; }
    else if (t < 768) { W = W1; Bh = w1h; K = 256;  N = 1024; lt = t - 512; }
    else              { W = W2; Bh = w2h; K = 1024; N = 256;  lt = t - 768; }
    const int ntn = N / 32;
    const int n0 = (lt % ntn) * 32, k0 = (lt / ntn) * 32;
    const int tx = threadIdx.x, ty = threadIdx.y;   // 32 x 8
#pragma unroll
    for (int j = 0; j < 4; j++)
        ts[ty + j * 8][tx] = W[(size_t)(k0 + ty + j * 8) * N + n0 + tx];
    __syncthreads();
#pragma unroll
    for (int j = 0; j < 4; j++)
        Bh[(size_t)(n0 + ty + j * 8) * K + k0 + tx] = __float2bfloat16(ts[tx][ty + j * 8]);
}

// ---------------------------------------------------------------------------
// Flash attention on tensor cores, single-pass bf16 throughout.
// One block per (b,n,h); 8 warps x 32 rows. V B-frags via ldmatrix.x4.trans.
// smem: Qh Kh Vh, 3 x 20480 (rows stride 80B -> conflict-free)
// ---------------------------------------------------------------------------
constexpr int ATT_SMEM = 3 * 20480;   // 61440

__global__ __launch_bounds__(256, 2)
void attn_tc(const bf16* __restrict__ qh, const bf16* __restrict__ kh,
             const bf16* __restrict__ vh, bf16* __restrict__ oh)
{
    extern __shared__ char smem[];
    const uint32_t sb = smem_to_u32(smem);
    const uint32_t Qh = sb, Kh = sb + 20480, Vh = sb + 40960;

    const int tid = threadIdx.x, wid = tid >> 5, lane = tid & 31;
    const int h = blockIdx.x & 7, bn = blockIdx.x >> 3;
    const size_t gbase = (size_t)bn * 256 * 256 + h * 32;

    for (int idx = tid; idx < 1024; idx += 256) {
        const int row = idx >> 2, c = idx & 3;
        const size_t g = gbase + (size_t)row * 256 + c * 8;
        const uint32_t so = row * 80 + c * 16;
        CP_ASYNC16(Qh + so, qh + g);
        CP_ASYNC16(Kh + so, kh + g);
        CP_ASYNC16(Vh + so, vh + g);
    }
    CP_ASYNC_COMMIT();
    asm volatile("cp.async.wait_group 0;" ::: "memory");
    __syncthreads();

    const int tq = lane >> 3, rin = lane & 7;
    const int aR  = (tq & 1) * 8 + rin;
    const int akh = tq >> 1;
    const int bR  = (tq >> 1) * 8 + rin;
    const int bkh = tq & 1;
    const int vrow  = (lane & 7) + ((lane >> 3) & 1) * 8;
    const int vcolb = ((lane >> 4) & 1) * 16;

    uint32_t qf[2][2][4];
#pragma unroll
    for (int mt = 0; mt < 2; mt++)
#pragma unroll
        for (int ks = 0; ks < 2; ks++) {
            const uint32_t ad = Qh + (uint32_t)((wid * 32 + mt * 16 + aR) * 80)
                              + (uint32_t)((ks * 2 + akh) * 16);
            ldsm4(ad, qf[mt][ks][0], qf[mt][ks][1], qf[mt][ks][2], qf[mt][ks][3]);
        }

    float O[2][4][4];
#pragma unroll
    for (int mt = 0; mt < 2; mt++)
#pragma unroll
        for (int j = 0; j < 4; j++)
#pragma unroll
            for (int r = 0; r < 4; r++) O[mt][j][r] = 0.f;
    float mrow[2][2] = { {-1e30f, -1e30f}, {-1e30f, -1e30f} };
    float lrow[2][2] = { {0.f, 0.f}, {0.f, 0.f} };

    for (int s0 = 0; s0 < 256; s0 += 64) {
        float acc[2][8][4];
#pragma unroll
        for (int mt = 0; mt < 2; mt++)
#pragma unroll
            for (int j = 0; j < 8; j++)
#pragma unroll
                for (int r = 0; r < 4; r++) acc[mt][j][r] = 0.f;

#pragma unroll
        for (int ks = 0; ks < 2; ks++) {
            uint32_t kb[8][2];
#pragma unroll
            for (int g = 0; g < 4; g++) {
                const uint32_t kd = Kh + (uint32_t)((s0 + g * 16 + bR) * 80)
                                  + (uint32_t)((ks * 2 + bkh) * 16);
                uint32_t r0, r1, r2, r3;
                ldsm4(kd, r0, r1, r2, r3);
                kb[g * 2][0] = r0; kb[g * 2][1] = r1;
                kb[g * 2 + 1][0] = r2; kb[g * 2 + 1][1] = r3;
            }
#pragma unroll
            for (int mt = 0; mt < 2; mt++)
#pragma unroll
                for (int j = 0; j < 8; j++)
                    mma_bf16(acc[mt][j], qf[mt][ks], kb[j]);
        }

#pragma unroll
        for (int mt = 0; mt < 2; mt++) {
            float mxA = -1e30f, mxB = -1e30f;
#pragma unroll
            for (int j = 0; j < 8; j++) {
                mxA = fmaxf(mxA, fmaxf(acc[mt][j][0], acc[mt][j][1]));
                mxB = fmaxf(mxB, fmaxf(acc[mt][j][2], acc[mt][j][3]));
            }
            mxA = fmaxf(mxA, __shfl_xor_sync(0xffffffffu, mxA, 1));
            mxA = fmaxf(mxA, __shfl_xor_sync(0xffffffffu, mxA, 2));
            mxB = fmaxf(mxB, __shfl_xor_sync(0xffffffffu, mxB, 1));
            mxB = fmaxf(mxB, __shfl_xor_sync(0xffffffffu, mxB, 2));
            const float mnA = fmaxf(mrow[mt][0], mxA);
            const float mnB = fmaxf(mrow[mt][1], mxB);
            const float fA = __expf(mrow[mt][0] - mnA);
            const float fB = __expf(mrow[mt][1] - mnB);
            mrow[mt][0] = mnA; mrow[mt][1] = mnB;
            float sA = 0.f, sB = 0.f;
#pragma unroll
            for (int j = 0; j < 8; j++) {
                acc[mt][j][0] = __expf(acc[mt][j][0] - mnA);
                acc[mt][j][1] = __expf(acc[mt][j][1] - mnA);
                acc[mt][j][2] = __expf(acc[mt][j][2] - mnB);
                acc[mt][j][3] = __expf(acc[mt][j][3] - mnB);
                sA += acc[mt][j][0] + acc[mt][j][1];
                sB += acc[mt][j][2] + acc[mt][j][3];
            }
            lrow[mt][0] = lrow[mt][0] * fA + sA;
            lrow[mt][1] = lrow[mt][1] * fB + sB;
#pragma unroll
            for (int j = 0; j < 4; j++) {
                O[mt][j][0] *= fA; O[mt][j][1] *= fA;
                O[mt][j][2] *= fB; O[mt][j][3] *= fB;
            }
        }

#pragma unroll
        for (int kt = 0; kt < 4; kt++) {
            uint32_t vb[4][2];
#pragma unroll
            for (int nb = 0; nb < 2; nb++) {
                const uint32_t vd = Vh + (uint32_t)((s0 + kt * 16 + vrow) * 80)
                                  + (uint32_t)(nb * 32 + vcolb);
                uint32_t r0, r1, r2, r3;
                ldsm4t(vd, r0, r1, r2, r3);
                vb[nb * 2][0] = r0; vb[nb * 2][1] = r1;
                vb[nb * 2 + 1][0] = r2; vb[nb * 2 + 1][1] = r3;
            }
#pragma unroll
            for (int mt = 0; mt < 2; mt++) {
                uint32_t ph[4];
#pragma unroll
                for (int half = 0; half < 2; half++) {
                    const int j = 2 * kt + half;
                    ph[half * 2 + 0] = pack2(__float2bfloat16(acc[mt][j][0]),
                                             __float2bfloat16(acc[mt][j][1]));
                    ph[half * 2 + 1] = pack2(__float2bfloat16(acc[mt][j][2]),
                                             __float2bfloat16(acc[mt][j][3]));
                }
#pragma unroll
                for (int j2 = 0; j2 < 4; j2++)
                    mma_bf16(O[mt][j2], ph, vb[j2]);
            }
        }
    }

#pragma unroll
    for (int mt = 0; mt < 2; mt++) {
        float lA = lrow[mt][0], lB = lrow[mt][1];
        lA += __shfl_xor_sync(0xffffffffu, lA, 1);
        lA += __shfl_xor_sync(0xffffffffu, lA, 2);
        lB += __shfl_xor_sync(0xffffffffu, lB, 1);
        lB += __shfl_xor_sync(0xffffffffu, lB, 2);
        const float invA = 1.f / lA, invB = 1.f / lB;
        const int rowA = wid * 32 + mt * 16 + (lane >> 2);
        const size_t gA = gbase + (size_t)rowA * 256;
        const size_t gB = gA + (size_t)8 * 256;
#pragma unroll
        for (int j2 = 0; j2 < 4; j2++) {
            const int col = j2 * 8 + (lane & 3) * 2;
            *(uint32_t*)&oh[gA + col] = pack2(__float2bfloat16(O[mt][j2][0] * invA),
                                              __float2bfloat16(O[mt][j2][1] * invA));
            *(uint32_t*)&oh[gB + col] = pack2(__float2bfloat16(O[mt][j2][2] * invB),
                                              __float2bfloat16(O[mt][j2][3] * invB));
        }
    }
}

// ---------------------------------------------------------------------------
// LayerNorm (D=256). Optionally emits bf16 hi of the normalized output.
// ---------------------------------------------------------------------------
template<bool EMIT>
__global__ __launch_bounds__(256)
void ln_k(const float* __restrict__ X, const float* __restrict__ g,
          const float* __restrict__ be, float* __restrict__ Y,
          bf16* __restrict__ Yh)
{
    const int r    = blockIdx.x * 8 + (threadIdx.x >> 5);
    const int lane = threadIdx.x & 31;
    const float* xr = X + (long long)r * D;

    float xv[8];
    float s = 0.f, ss = 0.f;
#pragma unroll
    for (int j = 0; j < 8; j++) {
        const float t = xr[lane + j * 32];
        xv[j] = t; s += t; ss += t * t;
    }
#pragma unroll
    for (int ofs = 16; ofs > 0; ofs >>= 1) {
        s  += __shfl_xor_sync(0xffffffffu, s,  ofs);
        ss += __shfl_xor_sync(0xffffffffu, ss, ofs);
    }
    const float mu  = s * (1.f / 256.f);
    const float var = ss * (1.f / 256.f) - mu * mu;
    const float rs  = rsqrtf(var + 1e-5f);

#pragma unroll
    for (int j = 0; j < 8; j++) {
        const int d = lane + j * 32;
        const float y = (xv[j] - mu) * rs * g[d] + be[d];
        Y[(long long)r * D + d] = y;
        if (EMIT) Yh[(long long)r * D + d] = __float2bfloat16(y);
    }
}

// ---------------------------------------------------------------------------
extern "C" void kernel_launch(void* const* d_in, const int* in_sizes, int n_in,
                              void* d_out, int out_size)
{
    const float* x   = (const float*)d_in[0];
    const float* Wq  = (const float*)d_in[1];
    const float* bq  = (const float*)d_in[2];
    const float* Wk  = (const float*)d_in[3];
    const float* bk  = (const float*)d_in[4];
    const float* Wv  = (const float*)d_in[5];
    const float* bv  = (const float*)d_in[6];
    const float* Wo  = (const float*)d_in[7];
    const float* bo  = (const float*)d_in[8];
    const float* W1  = (const float*)d_in[9];
    const float* b1  = (const float*)d_in[10];
    const float* W2  = (const float*)d_in[11];
    const float* b2  = (const float*)d_in[12];
    const float* g1  = (const float*)d_in[13];
    const float* be1 = (const float*)d_in[14];
    const float* g2  = (const float*)d_in[15];
    const float* be2 = (const float*)d_in[16];
    float* out = (float*)d_out;

    bf16 *xph, *xpl, *qh, *kh, *vh, *aoh, *hh, *ffh;
    bf16 *wqh, *wkh, *wvh, *woh, *w1h, *w2h;
    float *sb, *hbuf;
    cudaGetSymbolAddress((void**)&xph, g_xph); cudaGetSymbolAddress((void**)&xpl, g_xpl);
    cudaGetSymbolAddress((void**)&qh,  g_qh);  cudaGetSymbolAddress((void**)&kh,  g_kh);
    cudaGetSymbolAddress((void**)&vh,  g_vh);  cudaGetSymbolAddress((void**)&aoh, g_aoh);
    cudaGetSymbolAddress((void**)&sb,  g_s);   cudaGetSymbolAddress((void**)&hbuf, g_h);
    cudaGetSymbolAddress((void**)&hh,  g_hh);  cudaGetSymbolAddress((void**)&ffh, g_ffh);
    cudaGetSymbolAddress((void**)&wqh, g_wqh); cudaGetSymbolAddress((void**)&wkh, g_wkh);
    cudaGetSymbolAddress((void**)&wvh, g_wvh); cudaGetSymbolAddress((void**)&woh, g_woh);
    cudaGetSymbolAddress((void**)&w1h, g_w1h); cudaGetSymbolAddress((void**)&w2h, g_w2h);

    constexpr int GSMEM2 = 3 * 24576;   // 2-pass stages
    constexpr int GSMEM1 = 3 * 16384;   // 1-pass stages
    cudaFuncSetAttribute(gemm_tc<4, true, 2>,  cudaFuncAttributeMaxDynamicSharedMemorySize, GSMEM2);
    cudaFuncSetAttribute(gemm_tc<4, true, 1>,  cudaFuncAttributeMaxDynamicSharedMemorySize, GSMEM1);
    cudaFuncSetAttribute(gemm_tc<1, false, 1>, cudaFuncAttributeMaxDynamicSharedMemorySize, GSMEM1);
    cudaFuncSetAttribute(gemm_tc<2, false, 1>, cudaFuncAttributeMaxDynamicSharedMemorySize, GSMEM1);
    cudaFuncSetAttribute(attn_tc, cudaFuncAttributeMaxDynamicSharedMemorySize, ATT_SMEM);

    padcvt_x<<<(BN_ * SP * D) / 256, 256>>>(x, xph, xpl);
    wtall<<<1024, dim3(32, 8)>>>(Wq, Wk, Wv, Wo, W1, W2, wqh, wkh, wvh, woh, w1h, w2h);

    const dim3 gQK(D / 128, TOK / 128, 2);
    const dim3 gD (D / 128, TOK / 128);
    const dim3 gF (Fd / 128, TOK / 128);
    const float qscale = 0.17677669529663687f;   // 1/sqrt(32)

    // Q+K fused (3-tap conv, 2-pass, hi out; Q pre-scaled).
    // NOTE: ldB = 3*D (conv weights are [N][3*D]) — this was the R9 bug.
    gemm_tc<4, true, 2><<<gQK, 256, GSMEM2>>>(xph, xpl, D, wqh, 3 * D, D, 3, 0, qscale,
                                              bq, nullptr, nullptr, qh, D,
                                              wkh, bk, 1.f, kh);
    // V (1-pass, hi out)
    gemm_tc<4, true, 1><<<gD, 256, GSMEM1>>>(xph, nullptr, D, wvh, D, D, 1, 1, 1.f,
                                             bv, nullptr, nullptr, vh, D,
                                             nullptr, nullptr, 0.f, nullptr);
    // attention (single-pass bf16)
    attn_tc<<<Bd * S1 * Hh, 256, ATT_SMEM>>>(qh, kh, vh, aoh);
    // s = x + ao@Wo + bo (1-pass)
    gemm_tc<1, false, 1><<<gD, 256, GSMEM1>>>(aoh, nullptr, D, woh, D, D, 1, 0, 1.f,
                                              bo, x, sb, nullptr, D,
                                              nullptr, nullptr, 0.f, nullptr);
    ln_k<true><<<TOK / 8, 256>>>(sb, g1, be1, hbuf, hh);
    // ff = leaky(h@W1 + b1) (1-pass, hi out)
    gemm_tc<2, false, 1><<<gF, 256, GSMEM1>>>(hh, nullptr, D, w1h, D, D, 1, 0, 1.f,
                                              b1, nullptr, nullptr, ffh, Fd,
                                              nullptr, nullptr, 0.f, nullptr);
    // s = h + ff@W2 + b2 (1-pass)
    gemm_tc<1, false, 1><<<gD, 256, GSMEM1>>>(ffh, nullptr, Fd, w2h, Fd, Fd, 1, 0, 1.f,
                                              b2, hbuf, sb, nullptr, D,
                                              nullptr, nullptr, 0.f, nullptr);
    ln_k<false><<<TOK / 8, 256>>>(sb, g2, be2, out, nullptr);
}

// round 11
// speedup vs baseline: 2.1068x; 1.0467x over previous
#include <cuda_runtime.h>
#include <cuda_bf16.h>
#include <cstdint>
#include <math.h>

using bf16 = __nv_bfloat16;

// ---------------- problem constants ----------------
constexpr int Bd  = 4;
constexpr int S1  = 64;
constexpr int S2  = 256;
constexpr int D   = 256;
constexpr int Hh  = 8;
constexpr int HD  = 32;
constexpr int Fd  = 1024;
constexpr int TOK = Bd * S1 * S2;     // 65536
constexpr int BN_ = Bd * S1;          // 256
constexpr int SP  = S2 + 2;           // padded time length 258

// ---------------- scratch (device globals) ----------------
__device__ bf16  g_xph[BN_ * SP * D];
__device__ bf16  g_xpl[BN_ * SP * D];
__device__ bf16  g_qh [TOK * D];
__device__ bf16  g_kh [TOK * D];
__device__ bf16  g_vh [TOK * D];
__device__ bf16  g_aoh[TOK * D];
__device__ float g_s  [TOK * D];
__device__ float g_h  [TOK * D];
__device__ bf16  g_hh [TOK * D];
__device__ bf16  g_ffh[TOK * Fd];
// transposed weights (hi only)
__device__ bf16 g_wqh[D * 3 * D];
__device__ bf16 g_wkh[D * 3 * D];
__device__ bf16 g_wvh[D * D];
__device__ bf16 g_woh[D * D];
__device__ bf16 g_w1h[Fd * D];
__device__ bf16 g_w2h[D * Fd];

// ---------------- helpers ----------------
__device__ __forceinline__ uint32_t smem_to_u32(const void* p) {
    uint32_t a;
    asm("{ .reg .u64 t; cvta.to.shared.u64 t, %1; cvt.u32.u64 %0, t; }" : "=r"(a) : "l"(p));
    return a;
}
#define CP_ASYNC16(s, g) \
    asm volatile("cp.async.cg.shared.global [%0], [%1], 16;" :: "r"((uint32_t)(s)), "l"(g))
#define CP_ASYNC_COMMIT() asm volatile("cp.async.commit_group;" ::: "memory")

__device__ __forceinline__ void ldsm4(uint32_t addr, uint32_t& r0, uint32_t& r1,
                                      uint32_t& r2, uint32_t& r3) {
    asm volatile("ldmatrix.sync.aligned.m8n8.x4.shared.b16 {%0,%1,%2,%3}, [%4];"
                 : "=r"(r0), "=r"(r1), "=r"(r2), "=r"(r3) : "r"(addr));
}
__device__ __forceinline__ void ldsm4t(uint32_t addr, uint32_t& r0, uint32_t& r1,
                                       uint32_t& r2, uint32_t& r3) {
    asm volatile("ldmatrix.sync.aligned.m8n8.x4.trans.shared.b16 {%0,%1,%2,%3}, [%4];"
                 : "=r"(r0), "=r"(r1), "=r"(r2), "=r"(r3) : "r"(addr));
}
__device__ __forceinline__ void mma_bf16(float* c, const uint32_t* a, const uint32_t* b) {
    asm volatile("mma.sync.aligned.m16n8k16.row.col.f32.bf16.bf16.f32 "
                 "{%0,%1,%2,%3}, {%4,%5,%6,%7}, {%8,%9}, {%0,%1,%2,%3};"
                 : "+f"(c[0]), "+f"(c[1]), "+f"(c[2]), "+f"(c[3])
                 : "r"(a[0]), "r"(a[1]), "r"(a[2]), "r"(a[3]), "r"(b[0]), "r"(b[1]));
}
__device__ __forceinline__ void split_bf16(float v, bf16& h, bf16& l) {
    h = __float2bfloat16(v);
    l = __float2bfloat16(v - __bfloat162float(h));
}
__device__ __forceinline__ uint32_t pack2(bf16 a, bf16 b) {
    __nv_bfloat162 p; p.x = a; p.y = b;
    return *(uint32_t*)&p;
}
// 64B-row swizzle (BK=32): 4 16B cols, rotate by (row>>1)&3
__device__ __forceinline__ uint32_t sw64(int row, int c) {
    return (uint32_t)(row * 64 + ((c ^ ((row >> 1) & 3)) << 4));
}
// 128B-row swizzle (BK=64): 8 16B cols, XOR by row&7 (SW128)
__device__ __forceinline__ uint32_t sw128r(int row, int c) {
    return (uint32_t)(row * 128 + ((c ^ (row & 7)) << 4));
}

// ---------------------------------------------------------------------------
// Tensor-core GEMM via mma.sync bf16, 128x128 block tile, BK = KB (32 or 64),
// NPASS accumulating passes (2: Ah*Bh + Al*Bh ; 1: Ah*Bh), 3-stage cp.async
// pipeline, 2 CTAs/SM. gridDim.z == 2 -> blockIdx.z picks second set (Q/K).
// KB=32 stage: [Ah 8K][Al 8K if NPASS==2][Bh 8K] (64B rows, sw64)
// KB=64 stage: [Ah 16K][Bh 16K]                   (128B rows, sw128r)
// EPI: 1 = bias*scl + R -> fp32 ; 2 = bias*scl + leaky -> bf16 hi ;
//      4 = bias*scl -> bf16 hi
// ---------------------------------------------------------------------------
template<int EPI, bool CONV, int NPASS, int KB>
__global__ __launch_bounds__(256, 2)
void gemm_tc(const bf16* __restrict__ Ah, const bf16* __restrict__ Al, int ldA,
             const bf16* Bh_, int ldB,
             int Ktap, int ntaps, int tapbase, float scl_,
             const float* bias_, const float* __restrict__ R,
             float* __restrict__ Cf, bf16* Ch_, int Nt,
             const bf16* Bh2, const float* bias2, float scl2, bf16* Ch2)
{
    constexpr int ATILE  = KB * 128 * 2 / 64 * 32;           // bytes: 128 rows * KB*2
    constexpr int STAGE  = (KB == 64) ? 32768 : ((NPASS == 2) ? 24576 : 16384);
    constexpr int BH_OFF = (KB == 64) ? 16384 : ((NPASS == 2) ? 16384 : 8192);
    constexpr int KSTEPS = KB / 16;
    (void)ATILE;

    extern __shared__ char smem[];
    const uint32_t sbase = smem_to_u32(smem);
    const int tid = threadIdx.x, wid = tid >> 5, lane = tid & 31;
    const int m0 = blockIdx.y * 128, n0 = blockIdx.x * 128;

    const bf16* Bh = Bh_;
    const float* bias = bias_;  float scl = scl_;
    bf16* Ch = Ch_;
    if (blockIdx.z == 1) { Bh = Bh2; bias = bias2; scl = scl2; Ch = Ch2; }

    int rowbase;
    if (CONV) { const int bn = m0 >> 8; const int t0 = m0 & 255; rowbase = bn * SP + t0 + tapbase; }
    else      { rowbase = m0; }

    const int kcpt = Ktap / KB;
    const int nch  = ntaps * kcpt;

    auto load_chunk = [&](int c, int stage) {
        const int tap = c / kcpt;
        const int kt  = (c - tap * kcpt) * KB;
        const uint32_t st = sbase + stage * STAGE;
        if (KB == 64) {
            const int c8 = tid & 7;           // 16B col 0..7
            const int rw = tid >> 3;          // 0..31
            const size_t aoff = (size_t)(rowbase + tap) * ldA + kt + c8 * 8;
            const size_t boff = (size_t)n0 * ldB + (size_t)tap * Ktap + kt + c8 * 8;
#pragma unroll
            for (int i = 0; i < 4; i++) {
                const int row = rw + i * 32;
                const uint32_t so = sw128r(row, c8);
                CP_ASYNC16(st +          so, Ah + aoff + (size_t)row * ldA);
                CP_ASYNC16(st + BH_OFF + so, Bh + boff + (size_t)row * ldB);
            }
        } else {
            const int c4 = tid & 3;           // 16B col 0..3
            const int rw = tid >> 2;          // 0..63
            const size_t aoff = (size_t)(rowbase + tap) * ldA + kt + c4 * 8;
            const size_t boff = (size_t)n0 * ldB + (size_t)tap * Ktap + kt + c4 * 8;
#pragma unroll
            for (int i = 0; i < 2; i++) {
                const int row = rw + i * 64;
                const uint32_t so = sw64(row, c4);
                CP_ASYNC16(st + so, Ah + aoff + (size_t)row * ldA);
                if (NPASS == 2)
                    CP_ASYNC16(st + 8192 + so, Al + aoff + (size_t)row * ldA);
                CP_ASYNC16(st + BH_OFF + so, Bh + boff + (size_t)row * ldB);
            }
        }
        CP_ASYNC_COMMIT();
    };

    load_chunk(0, 0);
    load_chunk(1, 1);

    const int wm  = wid & 1,  wn  = wid >> 1;
    const int m0w = wm * 64,  n0w = wn * 32;
    const int tq  = lane >> 3, rin = lane & 7;
    const int aRow = m0w + (tq & 1) * 8 + rin;
    const int akh  = tq >> 1;
    const int bRow = n0w + (tq >> 1) * 8 + rin;
    const int bkh  = tq & 1;

    float acc[4][4][4];
#pragma unroll
    for (int i = 0; i < 4; i++)
#pragma unroll
        for (int j = 0; j < 4; j++)
#pragma unroll
            for (int r = 0; r < 4; r++) acc[i][j][r] = 0.f;

    for (int c = 0; c < nch; c++) {
        if (c + 1 < nch) asm volatile("cp.async.wait_group 1;" ::: "memory");
        else             asm volatile("cp.async.wait_group 0;" ::: "memory");
        __syncthreads();
        if (c + 2 < nch) load_chunk(c + 2, (c + 2) % 3);

        const uint32_t Ab = sbase + (c % 3) * STAGE;
        const uint32_t Bb = Ab + BH_OFF;

#pragma unroll
        for (int ks = 0; ks < KSTEPS; ks++) {
            uint32_t ah[4][4], al[4][4], bh[4][2];
#pragma unroll
            for (int mt = 0; mt < 4; mt++) {
                const int r = aRow + mt * 16;
                const uint32_t ad = (KB == 64)
                    ? Ab + sw128r(r, (ks * 2 + akh) ^ rin ^ r & 0)  // placeholder, fixed below
                    : Ab + sw64(r, ks * 2 + akh);
                // KB==64: address col' = (ks*2+akh) ^ (r&7); r&7 == rin here
                const uint32_t ad64 = Ab + (uint32_t)(r * 128) + (uint32_t)((((ks * 2 + akh) ^ rin) & 7) << 4);
                const uint32_t aa = (KB == 64) ? ad64 : ad;
                ldsm4(aa, ah[mt][0], ah[mt][1], ah[mt][2], ah[mt][3]);
                if (NPASS == 2)
                    ldsm4(aa + 8192, al[mt][0], al[mt][1], al[mt][2], al[mt][3]);
            }
#pragma unroll
            for (int nt2 = 0; nt2 < 2; nt2++) {
                const int r = bRow + nt2 * 16;
                const uint32_t bd = (KB == 64)
                    ? Bb + (uint32_t)(r * 128) + (uint32_t)((((ks * 2 + bkh) ^ rin) & 7) << 4)
                    : Bb + sw64(r, ks * 2 + bkh);
                uint32_t r0, r1, r2, r3;
                ldsm4(bd, r0, r1, r2, r3);
                bh[nt2 * 2][0] = r0; bh[nt2 * 2][1] = r1;
                bh[nt2 * 2 + 1][0] = r2; bh[nt2 * 2 + 1][1] = r3;
            }
#pragma unroll
            for (int mt = 0; mt < 4; mt++)
#pragma unroll
                for (int nt = 0; nt < 4; nt++) {
                    mma_bf16(acc[mt][nt], ah[mt], bh[nt]);
                    if (NPASS == 2)
                        mma_bf16(acc[mt][nt], al[mt], bh[nt]);
                }
        }
    }

    const int erow = lane >> 2;
    const int ecol = (lane & 3) * 2;
#pragma unroll
    for (int mt = 0; mt < 4; mt++) {
#pragma unroll
        for (int nt = 0; nt < 4; nt++) {
            const int col = n0 + n0w + nt * 8 + ecol;
            const float2 bi = *(const float2*)&bias[col];
#pragma unroll
            for (int half = 0; half < 2; half++) {
                const int row = m0 + m0w + mt * 16 + erow + half * 8;
                float v0 = (acc[mt][nt][half * 2 + 0] + bi.x) * scl;
                float v1 = (acc[mt][nt][half * 2 + 1] + bi.y) * scl;
                if (EPI == 1) {
                    const float2 rr = *(const float2*)&R[(size_t)row * Nt + col];
                    v0 += rr.x; v1 += rr.y;
                    float2 o; o.x = v0; o.y = v1;
                    *(float2*)&Cf[(size_t)row * Nt + col] = o;
                } else {
                    if (EPI == 2) {
                        v0 = v0 > 0.f ? v0 : 0.01f * v0;
                        v1 = v1 > 0.f ? v1 : 0.01f * v1;
                    }
                    *(uint32_t*)&Ch[(size_t)row * Nt + col] =
                        pack2(__float2bfloat16(v0), __float2bfloat16(v1));
                }
            }
        }
    }
}

// ---------------------------------------------------------------------------
// pad + split x into bf16 hi/lo padded buffer [bn][258][256]
// ---------------------------------------------------------------------------
__global__ __launch_bounds__(256)
void padcvt_x(const float* __restrict__ x, bf16* __restrict__ xh, bf16* __restrict__ xl)
{
    const size_t i = (size_t)blockIdx.x * 256 + threadIdx.x;
    const int d = (int)(i & 255);
    const size_t rest = i >> 8;
    const int t = (int)(rest % SP);
    const size_t bn = rest / SP;
    float v = 0.f;
    if (t >= 1 && t <= S2) v = x[(bn * S2 + (t - 1)) * D + d];
    bf16 h, l; split_bf16(v, h, l);
    xh[i] = h; xl[i] = l;
}

// ---------------------------------------------------------------------------
// fused weight transpose+convert (hi only): 6 weights in one launch
// ---------------------------------------------------------------------------
__global__ __launch_bounds__(256)
void wtall(const float* __restrict__ Wq, const float* __restrict__ Wk,
           const float* __restrict__ Wv, const float* __restrict__ Wo,
           const float* __restrict__ W1, const float* __restrict__ W2,
           bf16* wqh, bf16* wkh, bf16* wvh, bf16* woh, bf16* w1h, bf16* w2h)
{
    __shared__ float ts[32][33];
    const int t = blockIdx.x;
    const float* W; bf16* Bh; int K, N, lt;
    if      (t < 192) { W = Wq; Bh = wqh; K = 768;  N = 256;  lt = t; }
    else if (t < 384) { W = Wk; Bh = wkh; K = 768;  N = 256;  lt = t - 192; }
    else if (t < 448) { W = Wv; Bh = wvh; K = 256;  N = 256;  lt = t - 384; }
    else if (t < 512) { W = Wo; Bh = woh; K = 256;  N = 256;  lt = t - 448; }
    else if (t < 768) { W = W1; Bh = w1h; K = 256;  N = 1024; lt = t - 512; }
    else              { W = W2; Bh = w2h; K = 1024; N = 256;  lt = t - 768; }
    const int ntn = N / 32;
    const int n0 = (lt % ntn) * 32, k0 = (lt / ntn) * 32;
    const int tx = threadIdx.x, ty = threadIdx.y;   // 32 x 8
#pragma unroll
    for (int j = 0; j < 4; j++)
        ts[ty + j * 8][tx] = W[(size_t)(k0 + ty + j * 8) * N + n0 + tx];
    __syncthreads();
#pragma unroll
    for (int j = 0; j < 4; j++)
        Bh[(size_t)(n0 + ty + j * 8) * K + k0 + tx] = __float2bfloat16(ts[tx][ty + j * 8]);
}

// ---------------------------------------------------------------------------
// Flash attention on tensor cores, single-pass bf16 throughout.
// One block per (b,n,h); 8 warps x 32 rows. V B-frags via ldmatrix.x4.trans.
// smem: Qh Kh Vh, 3 x 20480 (rows stride 80B -> conflict-free)
// ---------------------------------------------------------------------------
constexpr int ATT_SMEM = 3 * 20480;   // 61440

__global__ __launch_bounds__(256, 2)
void attn_tc(const bf16* __restrict__ qh, const bf16* __restrict__ kh,
             const bf16* __restrict__ vh, bf16* __restrict__ oh)
{
    extern __shared__ char smem[];
    const uint32_t sb = smem_to_u32(smem);
    const uint32_t Qh = sb, Kh = sb + 20480, Vh = sb + 40960;

    const int tid = threadIdx.x, wid = tid >> 5, lane = tid & 31;
    const int h = blockIdx.x & 7, bn = blockIdx.x >> 3;
    const size_t gbase = (size_t)bn * 256 * 256 + h * 32;

    for (int idx = tid; idx < 1024; idx += 256) {
        const int row = idx >> 2, c = idx & 3;
        const size_t g = gbase + (size_t)row * 256 + c * 8;
        const uint32_t so = row * 80 + c * 16;
        CP_ASYNC16(Qh + so, qh + g);
        CP_ASYNC16(Kh + so, kh + g);
        CP_ASYNC16(Vh + so, vh + g);
    }
    CP_ASYNC_COMMIT();
    asm volatile("cp.async.wait_group 0;" ::: "memory");
    __syncthreads();

    const int tq = lane >> 3, rin = lane & 7;
    const int aR  = (tq & 1) * 8 + rin;
    const int akh = tq >> 1;
    const int bR  = (tq >> 1) * 8 + rin;
    const int bkh = tq & 1;
    const int vrow  = (lane & 7) + ((lane >> 3) & 1) * 8;
    const int vcolb = ((lane >> 4) & 1) * 16;

    uint32_t qf[2][2][4];
#pragma unroll
    for (int mt = 0; mt < 2; mt++)
#pragma unroll
        for (int ks = 0; ks < 2; ks++) {
            const uint32_t ad = Qh + (uint32_t)((wid * 32 + mt * 16 + aR) * 80)
                              + (uint32_t)((ks * 2 + akh) * 16);
            ldsm4(ad, qf[mt][ks][0], qf[mt][ks][1], qf[mt][ks][2], qf[mt][ks][3]);
        }

    float O[2][4][4];
#pragma unroll
    for (int mt = 0; mt < 2; mt++)
#pragma unroll
        for (int j = 0; j < 4; j++)
#pragma unroll
            for (int r = 0; r < 4; r++) O[mt][j][r] = 0.f;
    float mrow[2][2] = { {-1e30f, -1e30f}, {-1e30f, -1e30f} };
    float lrow[2][2] = { {0.f, 0.f}, {0.f, 0.f} };

    for (int s0 = 0; s0 < 256; s0 += 64) {
        float acc[2][8][4];
#pragma unroll
        for (int mt = 0; mt < 2; mt++)
#pragma unroll
            for (int j = 0; j < 8; j++)
#pragma unroll
                for (int r = 0; r < 4; r++) acc[mt][j][r] = 0.f;

#pragma unroll
        for (int ks = 0; ks < 2; ks++) {
            uint32_t kb[8][2];
#pragma unroll
            for (int g = 0; g < 4; g++) {
                const uint32_t kd = Kh + (uint32_t)((s0 + g * 16 + bR) * 80)
                                  + (uint32_t)((ks * 2 + bkh) * 16);
                uint32_t r0, r1, r2, r3;
                ldsm4(kd, r0, r1, r2, r3);
                kb[g * 2][0] = r0; kb[g * 2][1] = r1;
                kb[g * 2 + 1][0] = r2; kb[g * 2 + 1][1] = r3;
            }
#pragma unroll
            for (int mt = 0; mt < 2; mt++)
#pragma unroll
                for (int j = 0; j < 8; j++)
                    mma_bf16(acc[mt][j], qf[mt][ks], kb[j]);
        }

#pragma unroll
        for (int mt = 0; mt < 2; mt++) {
            float mxA = -1e30f, mxB = -1e30f;
#pragma unroll
            for (int j = 0; j < 8; j++) {
                mxA = fmaxf(mxA, fmaxf(acc[mt][j][0], acc[mt][j][1]));
                mxB = fmaxf(mxB, fmaxf(acc[mt][j][2], acc[mt][j][3]));
            }
            mxA = fmaxf(mxA, __shfl_xor_sync(0xffffffffu, mxA, 1));
            mxA = fmaxf(mxA, __shfl_xor_sync(0xffffffffu, mxA, 2));
            mxB = fmaxf(mxB, __shfl_xor_sync(0xffffffffu, mxB, 1));
            mxB = fmaxf(mxB, __shfl_xor_sync(0xffffffffu, mxB, 2));
            const float mnA = fmaxf(mrow[mt][0], mxA);
            const float mnB = fmaxf(mrow[mt][1], mxB);
            const float fA = __expf(mrow[mt][0] - mnA);
            const float fB = __expf(mrow[mt][1] - mnB);
            mrow[mt][0] = mnA; mrow[mt][1] = mnB;
            float sA = 0.f, sB = 0.f;
#pragma unroll
            for (int j = 0; j < 8; j++) {
                acc[mt][j][0] = __expf(acc[mt][j][0] - mnA);
                acc[mt][j][1] = __expf(acc[mt][j][1] - mnA);
                acc[mt][j][2] = __expf(acc[mt][j][2] - mnB);
                acc[mt][j][3] = __expf(acc[mt][j][3] - mnB);
                sA += acc[mt][j][0] + acc[mt][j][1];
                sB += acc[mt][j][2] + acc[mt][j][3];
            }
            lrow[mt][0] = lrow[mt][0] * fA + sA;
            lrow[mt][1] = lrow[mt][1] * fB + sB;
#pragma unroll
            for (int j = 0; j < 4; j++) {
                O[mt][j][0] *= fA; O[mt][j][1] *= fA;
                O[mt][j][2] *= fB; O[mt][j][3] *= fB;
            }
        }

#pragma unroll
        for (int kt = 0; kt < 4; kt++) {
            uint32_t vb[4][2];
#pragma unroll
            for (int nb = 0; nb < 2; nb++) {
                const uint32_t vd = Vh + (uint32_t)((s0 + kt * 16 + vrow) * 80)
                                  + (uint32_t)(nb * 32 + vcolb);
                uint32_t r0, r1, r2, r3;
                ldsm4t(vd, r0, r1, r2, r3);
                vb[nb * 2][0] = r0; vb[nb * 2][1] = r1;
                vb[nb * 2 + 1][0] = r2; vb[nb * 2 + 1][1] = r3;
            }
#pragma unroll
            for (int mt = 0; mt < 2; mt++) {
                uint32_t ph[4];
#pragma unroll
                for (int half = 0; half < 2; half++) {
                    const int j = 2 * kt + half;
                    ph[half * 2 + 0] = pack2(__float2bfloat16(acc[mt][j][0]),
                                             __float2bfloat16(acc[mt][j][1]));
                    ph[half * 2 + 1] = pack2(__float2bfloat16(acc[mt][j][2]),
                                             __float2bfloat16(acc[mt][j][3]));
                }
#pragma unroll
                for (int j2 = 0; j2 < 4; j2++)
                    mma_bf16(O[mt][j2], ph, vb[j2]);
            }
        }
    }

#pragma unroll
    for (int mt = 0; mt < 2; mt++) {
        float lA = lrow[mt][0], lB = lrow[mt][1];
        lA += __shfl_xor_sync(0xffffffffu, lA, 1);
        lA += __shfl_xor_sync(0xffffffffu, lA, 2);
        lB += __shfl_xor_sync(0xffffffffu, lB, 1);
        lB += __shfl_xor_sync(0xffffffffu, lB, 2);
        const float invA = 1.f / lA, invB = 1.f / lB;
        const int rowA = wid * 32 + mt * 16 + (lane >> 2);
        const size_t gA = gbase + (size_t)rowA * 256;
        const size_t gB = gA + (size_t)8 * 256;
#pragma unroll
        for (int j2 = 0; j2 < 4; j2++) {
            const int col = j2 * 8 + (lane & 3) * 2;
            *(uint32_t*)&oh[gA + col] = pack2(__float2bfloat16(O[mt][j2][0] * invA),
                                              __float2bfloat16(O[mt][j2][1] * invA));
            *(uint32_t*)&oh[gB + col] = pack2(__float2bfloat16(O[mt][j2][2] * invB),
                                              __float2bfloat16(O[mt][j2][3] * invB));
        }
    }
}

// ---------------------------------------------------------------------------
// LayerNorm (D=256). Optionally emits bf16 hi of the normalized output.
// ---------------------------------------------------------------------------
template<bool EMIT>
__global__ __launch_bounds__(256)
void ln_k(const float* __restrict__ X, const float* __restrict__ g,
          const float* __restrict__ be, float* __restrict__ Y,
          bf16* __restrict__ Yh)
{
    const int r    = blockIdx.x * 8 + (threadIdx.x >> 5);
    const int lane = threadIdx.x & 31;
    const float* xr = X + (long long)r * D;

    float xv[8];
    float s = 0.f, ss = 0.f;
#pragma unroll
    for (int j = 0; j < 8; j++) {
        const float t = xr[lane + j * 32];
        xv[j] = t; s += t; ss += t * t;
    }
#pragma unroll
    for (int ofs = 16; ofs > 0; ofs >>= 1) {
        s  += __shfl_xor_sync(0xffffffffu, s,  ofs);
        ss += __shfl_xor_sync(0xffffffffu, ss, ofs);
    }
    const float mu  = s * (1.f / 256.f);
    const float var = ss * (1.f / 256.f) - mu * mu;
    const float rs  = rsqrtf(var + 1e-5f);

#pragma unroll
    for (int j = 0; j < 8; j++) {
        const int d = lane + j * 32;
        const float y = (xv[j] - mu) * rs * g[d] + be[d];
        Y[(long long)r * D + d] = y;
        if (EMIT) Yh[(long long)r * D + d] = __float2bfloat16(y);
    }
}

// ---------------------------------------------------------------------------
extern "C" void kernel_launch(void* const* d_in, const int* in_sizes, int n_in,
                              void* d_out, int out_size)
{
    const float* x   = (const float*)d_in[0];
    const float* Wq  = (const float*)d_in[1];
    const float* bq  = (const float*)d_in[2];
    const float* Wk  = (const float*)d_in[3];
    const float* bk  = (const float*)d_in[4];
    const float* Wv  = (const float*)d_in[5];
    const float* bv  = (const float*)d_in[6];
    const float* Wo  = (const float*)d_in[7];
    const float* bo  = (const float*)d_in[8];
    const float* W1  = (const float*)d_in[9];
    const float* b1  = (const float*)d_in[10];
    const float* W2  = (const float*)d_in[11];
    const float* b2  = (const float*)d_in[12];
    const float* g1  = (const float*)d_in[13];
    const float* be1 = (const float*)d_in[14];
    const float* g2  = (const float*)d_in[15];
    const float* be2 = (const float*)d_in[16];
    float* out = (float*)d_out;

    bf16 *xph, *xpl, *qh, *kh, *vh, *aoh, *hh, *ffh;
    bf16 *wqh, *wkh, *wvh, *woh, *w1h, *w2h;
    float *sb, *hbuf;
    cudaGetSymbolAddress((void**)&xph, g_xph); cudaGetSymbolAddress((void**)&xpl, g_xpl);
    cudaGetSymbolAddress((void**)&qh,  g_qh);  cudaGetSymbolAddress((void**)&kh,  g_kh);
    cudaGetSymbolAddress((void**)&vh,  g_vh);  cudaGetSymbolAddress((void**)&aoh, g_aoh);
    cudaGetSymbolAddress((void**)&sb,  g_s);   cudaGetSymbolAddress((void**)&hbuf, g_h);
    cudaGetSymbolAddress((void**)&hh,  g_hh);  cudaGetSymbolAddress((void**)&ffh, g_ffh);
    cudaGetSymbolAddress((void**)&wqh, g_wqh); cudaGetSymbolAddress((void**)&wkh, g_wkh);
    cudaGetSymbolAddress((void**)&wvh, g_wvh); cudaGetSymbolAddress((void**)&woh, g_woh);
    cudaGetSymbolAddress((void**)&w1h, g_w1h); cudaGetSymbolAddress((void**)&w2h, g_w2h);

    constexpr int GSMEM2  = 3 * 24576;   // 2-pass BK=32 stages
    constexpr int GSMEM64 = 3 * 32768;   // 1-pass BK=64 stages
    cudaFuncSetAttribute(gemm_tc<4, true, 2, 32>,  cudaFuncAttributeMaxDynamicSharedMemorySize, GSMEM2);
    cudaFuncSetAttribute(gemm_tc<4, true, 1, 64>,  cudaFuncAttributeMaxDynamicSharedMemorySize, GSMEM64);
    cudaFuncSetAttribute(gemm_tc<1, false, 1, 64>, cudaFuncAttributeMaxDynamicSharedMemorySize, GSMEM64);
    cudaFuncSetAttribute(gemm_tc<2, false, 1, 64>, cudaFuncAttributeMaxDynamicSharedMemorySize, GSMEM64);
    cudaFuncSetAttribute(attn_tc, cudaFuncAttributeMaxDynamicSharedMemorySize, ATT_SMEM);

    padcvt_x<<<(BN_ * SP * D) / 256, 256>>>(x, xph, xpl);
    wtall<<<1024, dim3(32, 8)>>>(Wq, Wk, Wv, Wo, W1, W2, wqh, wkh, wvh, woh, w1h, w2h);

    const dim3 gQK(D / 128, TOK / 128, 2);
    const dim3 gD (D / 128, TOK / 128);
    const dim3 gF (Fd / 128, TOK / 128);
    const float qscale = 0.17677669529663687f;   // 1/sqrt(32)

    // Q+K fused (3-tap conv, 2-pass, BK=32, hi out; Q pre-scaled; ldB = 3*D)
    gemm_tc<4, true, 2, 32><<<gQK, 256, GSMEM2>>>(xph, xpl, D, wqh, 3 * D, D, 3, 0, qscale,
                                                  bq, nullptr, nullptr, qh, D,
                                                  wkh, bk, 1.f, kh);
    // V (1-pass, BK=64, hi out)
    gemm_tc<4, true, 1, 64><<<gD, 256, GSMEM64>>>(xph, nullptr, D, wvh, D, D, 1, 1, 1.f,
                                                  bv, nullptr, nullptr, vh, D,
                                                  nullptr, nullptr, 0.f, nullptr);
    // attention (single-pass bf16)
    attn_tc<<<Bd * S1 * Hh, 256, ATT_SMEM>>>(qh, kh, vh, aoh);
    // s = x + ao@Wo + bo (1-pass, BK=64)
    gemm_tc<1, false, 1, 64><<<gD, 256, GSMEM64>>>(aoh, nullptr, D, woh, D, D, 1, 0, 1.f,
                                                   bo, x, sb, nullptr, D,
                                                   nullptr, nullptr, 0.f, nullptr);
    ln_k<true><<<TOK / 8, 256>>>(sb, g1, be1, hbuf, hh);
    // ff = leaky(h@W1 + b1) (1-pass, BK=64, hi out)
    gemm_tc<2, false, 1, 64><<<gF, 256, GSMEM64>>>(hh, nullptr, D, w1h, D, D, 1, 0, 1.f,
                                                   b1, nullptr, nullptr, ffh, Fd,
                                                   nullptr, nullptr, 0.f, nullptr);
    // s = h + ff@W2 + b2 (1-pass, BK=64)
    gemm_tc<1, false, 1, 64><<<gD, 256, GSMEM64>>>(ffh, nullptr, Fd, w2h, Fd, Fd, 1, 0, 1.f,
                                                   b2, hbuf, sb, nullptr, D,
                                                   nullptr, nullptr, 0.f, nullptr);
    ln_k<false><<<TOK / 8, 256>>>(sb, g2, be2, out, nullptr);
}

// round 12
// speedup vs baseline: 2.1167x; 1.0047x over previous
#include <cuda_runtime.h>
#include <cuda_bf16.h>
#include <cstdint>
#include <math.h>

using bf16 = __nv_bfloat16;

// ---------------- problem constants ----------------
constexpr int Bd  = 4;
constexpr int S1  = 64;
constexpr int S2  = 256;
constexpr int D   = 256;
constexpr int Hh  = 8;
constexpr int HD  = 32;
constexpr int Fd  = 1024;
constexpr int TOK = Bd * S1 * S2;     // 65536
constexpr int BN_ = Bd * S1;          // 256
constexpr int SP  = S2 + 2;           // padded time length 258

// ---------------- scratch (device globals) ----------------
__device__ bf16  g_xph[BN_ * SP * D];
__device__ bf16  g_xpl[BN_ * SP * D];
__device__ bf16  g_qh [TOK * D];
__device__ bf16  g_kh [TOK * D];
__device__ bf16  g_vh [TOK * D];
__device__ bf16  g_aoh[TOK * D];
__device__ float g_s  [TOK * D];
__device__ float g_h  [TOK * D];
__device__ bf16  g_hh [TOK * D];
__device__ bf16  g_ffh[TOK * Fd];
// transposed weights (hi only)
__device__ bf16 g_wqh[D * 3 * D];
__device__ bf16 g_wkh[D * 3 * D];
__device__ bf16 g_wvh[D * D];
__device__ bf16 g_woh[D * D];
__device__ bf16 g_w1h[Fd * D];
__device__ bf16 g_w2h[D * Fd];

// ---------------- helpers ----------------
__device__ __forceinline__ uint32_t smem_to_u32(const void* p) {
    uint32_t a;
    asm("{ .reg .u64 t; cvta.to.shared.u64 t, %1; cvt.u32.u64 %0, t; }" : "=r"(a) : "l"(p));
    return a;
}
#define CP_ASYNC16(s, g) \
    asm volatile("cp.async.cg.shared.global [%0], [%1], 16;" :: "r"((uint32_t)(s)), "l"(g))
#define CP_ASYNC_COMMIT() asm volatile("cp.async.commit_group;" ::: "memory")

__device__ __forceinline__ void ldsm4(uint32_t addr, uint32_t& r0, uint32_t& r1,
                                      uint32_t& r2, uint32_t& r3) {
    asm volatile("ldmatrix.sync.aligned.m8n8.x4.shared.b16 {%0,%1,%2,%3}, [%4];"
                 : "=r"(r0), "=r"(r1), "=r"(r2), "=r"(r3) : "r"(addr));
}
__device__ __forceinline__ void ldsm4t(uint32_t addr, uint32_t& r0, uint32_t& r1,
                                       uint32_t& r2, uint32_t& r3) {
    asm volatile("ldmatrix.sync.aligned.m8n8.x4.trans.shared.b16 {%0,%1,%2,%3}, [%4];"
                 : "=r"(r0), "=r"(r1), "=r"(r2), "=r"(r3) : "r"(addr));
}
__device__ __forceinline__ void mma_bf16(float* c, const uint32_t* a, const uint32_t* b) {
    asm volatile("mma.sync.aligned.m16n8k16.row.col.f32.bf16.bf16.f32 "
                 "{%0,%1,%2,%3}, {%4,%5,%6,%7}, {%8,%9}, {%0,%1,%2,%3};"
                 : "+f"(c[0]), "+f"(c[1]), "+f"(c[2]), "+f"(c[3])
                 : "r"(a[0]), "r"(a[1]), "r"(a[2]), "r"(a[3]), "r"(b[0]), "r"(b[1]));
}
__device__ __forceinline__ void split_bf16(float v, bf16& h, bf16& l) {
    h = __float2bfloat16(v);
    l = __float2bfloat16(v - __bfloat162float(h));
}
__device__ __forceinline__ uint32_t pack2(bf16 a, bf16 b) {
    __nv_bfloat162 p; p.x = a; p.y = b;
    return *(uint32_t*)&p;
}
// 64B-row swizzle (BK=32): 4 16B cols, rotate by (row>>1)&3
__device__ __forceinline__ uint32_t sw64(int row, int c) {
    return (uint32_t)(row * 64 + ((c ^ ((row >> 1) & 3)) << 4));
}
// 128B-row swizzle (BK=64): 8 16B cols, XOR by row&7 (SW128)
__device__ __forceinline__ uint32_t sw128r(int row, int c) {
    return (uint32_t)(row * 128 + ((c ^ (row & 7)) << 4));
}

// ---------------------------------------------------------------------------
// Tensor-core GEMM via mma.sync bf16, 128x128 block tile, BK = KB (32 or 64),
// NPASS accumulating passes (2: Ah*Bh + Al*Bh ; 1: Ah*Bh), 3-stage cp.async
// pipeline, 2 CTAs/SM. gridDim.z == 2 -> blockIdx.z picks second set (Q/K).
// KB=32 stage: [Ah 8K][Al 8K if NPASS==2][Bh 8K] (64B rows, sw64)
// KB=64 stage: [Ah 16K][Bh 16K]                   (128B rows, sw128r)
// EPI: 1 = bias*scl + R -> fp32 ; 2 = bias*scl + leaky -> bf16 hi ;
//      4 = bias*scl -> bf16 hi
// ---------------------------------------------------------------------------
template<int EPI, bool CONV, int NPASS, int KB>
__global__ __launch_bounds__(256, 2)
void gemm_tc(const bf16* __restrict__ Ah, const bf16* __restrict__ Al, int ldA,
             const bf16* Bh_, int ldB,
             int Ktap, int ntaps, int tapbase, float scl_,
             const float* bias_, const float* __restrict__ R,
             float* __restrict__ Cf, bf16* Ch_, int Nt,
             const bf16* Bh2, const float* bias2, float scl2, bf16* Ch2)
{
    constexpr int ATILE  = KB * 128 * 2 / 64 * 32;           // bytes: 128 rows * KB*2
    constexpr int STAGE  = (KB == 64) ? 32768 : ((NPASS == 2) ? 24576 : 16384);
    constexpr int BH_OFF = (KB == 64) ? 16384 : ((NPASS == 2) ? 16384 : 8192);
    constexpr int KSTEPS = KB / 16;
    (void)ATILE;

    extern __shared__ char smem[];
    const uint32_t sbase = smem_to_u32(smem);
    const int tid = threadIdx.x, wid = tid >> 5, lane = tid & 31;
    const int m0 = blockIdx.y * 128, n0 = blockIdx.x * 128;

    const bf16* Bh = Bh_;
    const float* bias = bias_;  float scl = scl_;
    bf16* Ch = Ch_;
    if (blockIdx.z == 1) { Bh = Bh2; bias = bias2; scl = scl2; Ch = Ch2; }

    int rowbase;
    if (CONV) { const int bn = m0 >> 8; const int t0 = m0 & 255; rowbase = bn * SP + t0 + tapbase; }
    else      { rowbase = m0; }

    const int kcpt = Ktap / KB;
    const int nch  = ntaps * kcpt;

    auto load_chunk = [&](int c, int stage) {
        const int tap = c / kcpt;
        const int kt  = (c - tap * kcpt) * KB;
        const uint32_t st = sbase + stage * STAGE;
        if (KB == 64) {
            const int c8 = tid & 7;           // 16B col 0..7
            const int rw = tid >> 3;          // 0..31
            const size_t aoff = (size_t)(rowbase + tap) * ldA + kt + c8 * 8;
            const size_t boff = (size_t)n0 * ldB + (size_t)tap * Ktap + kt + c8 * 8;
#pragma unroll
            for (int i = 0; i < 4; i++) {
                const int row = rw + i * 32;
                const uint32_t so = sw128r(row, c8);
                CP_ASYNC16(st +          so, Ah + aoff + (size_t)row * ldA);
                CP_ASYNC16(st + BH_OFF + so, Bh + boff + (size_t)row * ldB);
            }
        } else {
            const int c4 = tid & 3;           // 16B col 0..3
            const int rw = tid >> 2;          // 0..63
            const size_t aoff = (size_t)(rowbase + tap) * ldA + kt + c4 * 8;
            const size_t boff = (size_t)n0 * ldB + (size_t)tap * Ktap + kt + c4 * 8;
#pragma unroll
            for (int i = 0; i < 2; i++) {
                const int row = rw + i * 64;
                const uint32_t so = sw64(row, c4);
                CP_ASYNC16(st + so, Ah + aoff + (size_t)row * ldA);
                if (NPASS == 2)
                    CP_ASYNC16(st + 8192 + so, Al + aoff + (size_t)row * ldA);
                CP_ASYNC16(st + BH_OFF + so, Bh + boff + (size_t)row * ldB);
            }
        }
        CP_ASYNC_COMMIT();
    };

    load_chunk(0, 0);
    load_chunk(1, 1);

    const int wm  = wid & 1,  wn  = wid >> 1;
    const int m0w = wm * 64,  n0w = wn * 32;
    const int tq  = lane >> 3, rin = lane & 7;
    const int aRow = m0w + (tq & 1) * 8 + rin;
    const int akh  = tq >> 1;
    const int bRow = n0w + (tq >> 1) * 8 + rin;
    const int bkh  = tq & 1;

    float acc[4][4][4];
#pragma unroll
    for (int i = 0; i < 4; i++)
#pragma unroll
        for (int j = 0; j < 4; j++)
#pragma unroll
            for (int r = 0; r < 4; r++) acc[i][j][r] = 0.f;

    for (int c = 0; c < nch; c++) {
        if (c + 1 < nch) asm volatile("cp.async.wait_group 1;" ::: "memory");
        else             asm volatile("cp.async.wait_group 0;" ::: "memory");
        __syncthreads();
        if (c + 2 < nch) load_chunk(c + 2, (c + 2) % 3);

        const uint32_t Ab = sbase + (c % 3) * STAGE;
        const uint32_t Bb = Ab + BH_OFF;

#pragma unroll
        for (int ks = 0; ks < KSTEPS; ks++) {
            uint32_t ah[4][4], al[4][4], bh[4][2];
#pragma unroll
            for (int mt = 0; mt < 4; mt++) {
                const int r = aRow + mt * 16;
                const uint32_t ad = (KB == 64)
                    ? Ab + sw128r(r, (ks * 2 + akh) ^ rin ^ r & 0)  // placeholder, fixed below
                    : Ab + sw64(r, ks * 2 + akh);
                // KB==64: address col' = (ks*2+akh) ^ (r&7); r&7 == rin here
                const uint32_t ad64 = Ab + (uint32_t)(r * 128) + (uint32_t)((((ks * 2 + akh) ^ rin) & 7) << 4);
                const uint32_t aa = (KB == 64) ? ad64 : ad;
                ldsm4(aa, ah[mt][0], ah[mt][1], ah[mt][2], ah[mt][3]);
                if (NPASS == 2)
                    ldsm4(aa + 8192, al[mt][0], al[mt][1], al[mt][2], al[mt][3]);
            }
#pragma unroll
            for (int nt2 = 0; nt2 < 2; nt2++) {
                const int r = bRow + nt2 * 16;
                const uint32_t bd = (KB == 64)
                    ? Bb + (uint32_t)(r * 128) + (uint32_t)((((ks * 2 + bkh) ^ rin) & 7) << 4)
                    : Bb + sw64(r, ks * 2 + bkh);
                uint32_t r0, r1, r2, r3;
                ldsm4(bd, r0, r1, r2, r3);
                bh[nt2 * 2][0] = r0; bh[nt2 * 2][1] = r1;
                bh[nt2 * 2 + 1][0] = r2; bh[nt2 * 2 + 1][1] = r3;
            }
#pragma unroll
            for (int mt = 0; mt < 4; mt++)
#pragma unroll
                for (int nt = 0; nt < 4; nt++) {
                    mma_bf16(acc[mt][nt], ah[mt], bh[nt]);
                    if (NPASS == 2)
                        mma_bf16(acc[mt][nt], al[mt], bh[nt]);
                }
        }
    }

    const int erow = lane >> 2;
    const int ecol = (lane & 3) * 2;
#pragma unroll
    for (int mt = 0; mt < 4; mt++) {
#pragma unroll
        for (int nt = 0; nt < 4; nt++) {
            const int col = n0 + n0w + nt * 8 + ecol;
            const float2 bi = *(const float2*)&bias[col];
#pragma unroll
            for (int half = 0; half < 2; half++) {
                const int row = m0 + m0w + mt * 16 + erow + half * 8;
                float v0 = (acc[mt][nt][half * 2 + 0] + bi.x) * scl;
                float v1 = (acc[mt][nt][half * 2 + 1] + bi.y) * scl;
                if (EPI == 1) {
                    const float2 rr = *(const float2*)&R[(size_t)row * Nt + col];
                    v0 += rr.x; v1 += rr.y;
                    float2 o; o.x = v0; o.y = v1;
                    *(float2*)&Cf[(size_t)row * Nt + col] = o;
                } else {
                    if (EPI == 2) {
                        v0 = v0 > 0.f ? v0 : 0.01f * v0;
                        v1 = v1 > 0.f ? v1 : 0.01f * v1;
                    }
                    *(uint32_t*)&Ch[(size_t)row * Nt + col] =
                        pack2(__float2bfloat16(v0), __float2bfloat16(v1));
                }
            }
        }
    }
}

// ---------------------------------------------------------------------------
// pad + split x into bf16 hi/lo padded buffer [bn][258][256]
// ---------------------------------------------------------------------------
__global__ __launch_bounds__(256)
void padcvt_x(const float* __restrict__ x, bf16* __restrict__ xh, bf16* __restrict__ xl)
{
    const size_t i = (size_t)blockIdx.x * 256 + threadIdx.x;
    const int d = (int)(i & 255);
    const size_t rest = i >> 8;
    const int t = (int)(rest % SP);
    const size_t bn = rest / SP;
    float v = 0.f;
    if (t >= 1 && t <= S2) v = x[(bn * S2 + (t - 1)) * D + d];
    bf16 h, l; split_bf16(v, h, l);
    xh[i] = h; xl[i] = l;
}

// ---------------------------------------------------------------------------
// fused weight transpose+convert (hi only): 6 weights in one launch
// ---------------------------------------------------------------------------
__global__ __launch_bounds__(256)
void wtall(const float* __restrict__ Wq, const float* __restrict__ Wk,
           const float* __restrict__ Wv, const float* __restrict__ Wo,
           const float* __restrict__ W1, const float* __restrict__ W2,
           bf16* wqh, bf16* wkh, bf16* wvh, bf16* woh, bf16* w1h, bf16* w2h)
{
    __shared__ float ts[32][33];
    const int t = blockIdx.x;
    const float* W; bf16* Bh; int K, N, lt;
    if      (t < 192) { W = Wq; Bh = wqh; K = 768;  N = 256;  lt = t; }
    else if (t < 384) { W = Wk; Bh = wkh; K = 768;  N = 256;  lt = t - 192; }
    else if (t < 448) { W = Wv; Bh = wvh; K = 256;  N = 256;  lt = t - 384; }
    else if (t < 512) { W = Wo; Bh = woh; K = 256;  N = 256;  lt = t - 448; }
    else if (t < 768) { W = W1; Bh = w1h; K = 256;  N = 1024; lt = t - 512; }
    else              { W = W2; Bh = w2h; K = 1024; N = 256;  lt = t - 768; }
    const int ntn = N / 32;
    const int n0 = (lt % ntn) * 32, k0 = (lt / ntn) * 32;
    const int tx = threadIdx.x, ty = threadIdx.y;   // 32 x 8
#pragma unroll
    for (int j = 0; j < 4; j++)
        ts[ty + j * 8][tx] = W[(size_t)(k0 + ty + j * 8) * N + n0 + tx];
    __syncthreads();
#pragma unroll
    for (int j = 0; j < 4; j++)
        Bh[(size_t)(n0 + ty + j * 8) * K + k0 + tx] = __float2bfloat16(ts[tx][ty + j * 8]);
}

// ---------------------------------------------------------------------------
// Flash attention on tensor cores, single-pass bf16 throughout.
// One block per (b,n,h); 8 warps x 32 rows. V B-frags via ldmatrix.x4.trans.
// smem: Qh Kh Vh, 3 x 20480 (rows stride 80B -> conflict-free)
// ---------------------------------------------------------------------------
constexpr int ATT_SMEM = 3 * 20480;   // 61440

__global__ __launch_bounds__(256, 2)
void attn_tc(const bf16* __restrict__ qh, const bf16* __restrict__ kh,
             const bf16* __restrict__ vh, bf16* __restrict__ oh)
{
    extern __shared__ char smem[];
    const uint32_t sb = smem_to_u32(smem);
    const uint32_t Qh = sb, Kh = sb + 20480, Vh = sb + 40960;

    const int tid = threadIdx.x, wid = tid >> 5, lane = tid & 31;
    const int h = blockIdx.x & 7, bn = blockIdx.x >> 3;
    const size_t gbase = (size_t)bn * 256 * 256 + h * 32;

    for (int idx = tid; idx < 1024; idx += 256) {
        const int row = idx >> 2, c = idx & 3;
        const size_t g = gbase + (size_t)row * 256 + c * 8;
        const uint32_t so = row * 80 + c * 16;
        CP_ASYNC16(Qh + so, qh + g);
        CP_ASYNC16(Kh + so, kh + g);
        CP_ASYNC16(Vh + so, vh + g);
    }
    CP_ASYNC_COMMIT();
    asm volatile("cp.async.wait_group 0;" ::: "memory");
    __syncthreads();

    const int tq = lane >> 3, rin = lane & 7;
    const int aR  = (tq & 1) * 8 + rin;
    const int akh = tq >> 1;
    const int bR  = (tq >> 1) * 8 + rin;
    const int bkh = tq & 1;
    const int vrow  = (lane & 7) + ((lane >> 3) & 1) * 8;
    const int vcolb = ((lane >> 4) & 1) * 16;

    uint32_t qf[2][2][4];
#pragma unroll
    for (int mt = 0; mt < 2; mt++)
#pragma unroll
        for (int ks = 0; ks < 2; ks++) {
            const uint32_t ad = Qh + (uint32_t)((wid * 32 + mt * 16 + aR) * 80)
                              + (uint32_t)((ks * 2 + akh) * 16);
            ldsm4(ad, qf[mt][ks][0], qf[mt][ks][1], qf[mt][ks][2], qf[mt][ks][3]);
        }

    float O[2][4][4];
#pragma unroll
    for (int mt = 0; mt < 2; mt++)
#pragma unroll
        for (int j = 0; j < 4; j++)
#pragma unroll
            for (int r = 0; r < 4; r++) O[mt][j][r] = 0.f;
    float mrow[2][2] = { {-1e30f, -1e30f}, {-1e30f, -1e30f} };
    float lrow[2][2] = { {0.f, 0.f}, {0.f, 0.f} };

    for (int s0 = 0; s0 < 256; s0 += 64) {
        float acc[2][8][4];
#pragma unroll
        for (int mt = 0; mt < 2; mt++)
#pragma unroll
            for (int j = 0; j < 8; j++)
#pragma unroll
                for (int r = 0; r < 4; r++) acc[mt][j][r] = 0.f;

#pragma unroll
        for (int ks = 0; ks < 2; ks++) {
            uint32_t kb[8][2];
#pragma unroll
            for (int g = 0; g < 4; g++) {
                const uint32_t kd = Kh + (uint32_t)((s0 + g * 16 + bR) * 80)
                                  + (uint32_t)((ks * 2 + bkh) * 16);
                uint32_t r0, r1, r2, r3;
                ldsm4(kd, r0, r1, r2, r3);
                kb[g * 2][0] = r0; kb[g * 2][1] = r1;
                kb[g * 2 + 1][0] = r2; kb[g * 2 + 1][1] = r3;
            }
#pragma unroll
            for (int mt = 0; mt < 2; mt++)
#pragma unroll
                for (int j = 0; j < 8; j++)
                    mma_bf16(acc[mt][j], qf[mt][ks], kb[j]);
        }

#pragma unroll
        for (int mt = 0; mt < 2; mt++) {
            float mxA = -1e30f, mxB = -1e30f;
#pragma unroll
            for (int j = 0; j < 8; j++) {
                mxA = fmaxf(mxA, fmaxf(acc[mt][j][0], acc[mt][j][1]));
                mxB = fmaxf(mxB, fmaxf(acc[mt][j][2], acc[mt][j][3]));
            }
            mxA = fmaxf(mxA, __shfl_xor_sync(0xffffffffu, mxA, 1));
            mxA = fmaxf(mxA, __shfl_xor_sync(0xffffffffu, mxA, 2));
            mxB = fmaxf(mxB, __shfl_xor_sync(0xffffffffu, mxB, 1));
            mxB = fmaxf(mxB, __shfl_xor_sync(0xffffffffu, mxB, 2));
            const float mnA = fmaxf(mrow[mt][0], mxA);
            const float mnB = fmaxf(mrow[mt][1], mxB);
            const float fA = __expf(mrow[mt][0] - mnA);
            const float fB = __expf(mrow[mt][1] - mnB);
            mrow[mt][0] = mnA; mrow[mt][1] = mnB;
            float sA = 0.f, sB = 0.f;
#pragma unroll
            for (int j = 0; j < 8; j++) {
                acc[mt][j][0] = __expf(acc[mt][j][0] - mnA);
                acc[mt][j][1] = __expf(acc[mt][j][1] - mnA);
                acc[mt][j][2] = __expf(acc[mt][j][2] - mnB);
                acc[mt][j][3] = __expf(acc[mt][j][3] - mnB);
                sA += acc[mt][j][0] + acc[mt][j][1];
                sB += acc[mt][j][2] + acc[mt][j][3];
            }
            lrow[mt][0] = lrow[mt][0] * fA + sA;
            lrow[mt][1] = lrow[mt][1] * fB + sB;
#pragma unroll
            for (int j = 0; j < 4; j++) {
                O[mt][j][0] *= fA; O[mt][j][1] *= fA;
                O[mt][j][2] *= fB; O[mt][j][3] *= fB;
            }
        }

#pragma unroll
        for (int kt = 0; kt < 4; kt++) {
            uint32_t vb[4][2];
#pragma unroll
            for (int nb = 0; nb < 2; nb++) {
                const uint32_t vd = Vh + (uint32_t)((s0 + kt * 16 + vrow) * 80)
                                  + (uint32_t)(nb * 32 + vcolb);
                uint32_t r0, r1, r2, r3;
                ldsm4t(vd, r0, r1, r2, r3);
                vb[nb * 2][0] = r0; vb[nb * 2][1] = r1;
                vb[nb * 2 + 1][0] = r2; vb[nb * 2 + 1][1] = r3;
            }
#pragma unroll
            for (int mt = 0; mt < 2; mt++) {
                uint32_t ph[4];
#pragma unroll
                for (int half = 0; half < 2; half++) {
                    const int j = 2 * kt + half;
                    ph[half * 2 + 0] = pack2(__float2bfloat16(acc[mt][j][0]),
                                             __float2bfloat16(acc[mt][j][1]));
                    ph[half * 2 + 1] = pack2(__float2bfloat16(acc[mt][j][2]),
                                             __float2bfloat16(acc[mt][j][3]));
                }
#pragma unroll
                for (int j2 = 0; j2 < 4; j2++)
                    mma_bf16(O[mt][j2], ph, vb[j2]);
            }
        }
    }

#pragma unroll
    for (int mt = 0; mt < 2; mt++) {
        float lA = lrow[mt][0], lB = lrow[mt][1];
        lA += __shfl_xor_sync(0xffffffffu, lA, 1);
        lA += __shfl_xor_sync(0xffffffffu, lA, 2);
        lB += __shfl_xor_sync(0xffffffffu, lB, 1);
        lB += __shfl_xor_sync(0xffffffffu, lB, 2);
        const float invA = 1.f / lA, invB = 1.f / lB;
        const int rowA = wid * 32 + mt * 16 + (lane >> 2);
        const size_t gA = gbase + (size_t)rowA * 256;
        const size_t gB = gA + (size_t)8 * 256;
#pragma unroll
        for (int j2 = 0; j2 < 4; j2++) {
            const int col = j2 * 8 + (lane & 3) * 2;
            *(uint32_t*)&oh[gA + col] = pack2(__float2bfloat16(O[mt][j2][0] * invA),
                                              __float2bfloat16(O[mt][j2][1] * invA));
            *(uint32_t*)&oh[gB + col] = pack2(__float2bfloat16(O[mt][j2][2] * invB),
                                              __float2bfloat16(O[mt][j2][3] * invB));
        }
    }
}

// ---------------------------------------------------------------------------
// LayerNorm (D=256). Optionally emits bf16 hi of the normalized output.
// ---------------------------------------------------------------------------
template<bool EMIT>
__global__ __launch_bounds__(256)
void ln_k(const float* __restrict__ X, const float* __restrict__ g,
          const float* __restrict__ be, float* __restrict__ Y,
          bf16* __restrict__ Yh)
{
    const int r    = blockIdx.x * 8 + (threadIdx.x >> 5);
    const int lane = threadIdx.x & 31;
    const float* xr = X + (long long)r * D;

    float xv[8];
    float s = 0.f, ss = 0.f;
#pragma unroll
    for (int j = 0; j < 8; j++) {
        const float t = xr[lane + j * 32];
        xv[j] = t; s += t; ss += t * t;
    }
#pragma unroll
    for (int ofs = 16; ofs > 0; ofs >>= 1) {
        s  += __shfl_xor_sync(0xffffffffu, s,  ofs);
        ss += __shfl_xor_sync(0xffffffffu, ss, ofs);
    }
    const float mu  = s * (1.f / 256.f);
    const float var = ss * (1.f / 256.f) - mu * mu;
    const float rs  = rsqrtf(var + 1e-5f);

#pragma unroll
    for (int j = 0; j < 8; j++) {
        const int d = lane + j * 32;
        const float y = (xv[j] - mu) * rs * g[d] + be[d];
        Y[(long long)r * D + d] = y;
        if (EMIT) Yh[(long long)r * D + d] = __float2bfloat16(y);
    }
}

// ---------------------------------------------------------------------------
extern "C" void kernel_launch(void* const* d_in, const int* in_sizes, int n_in,
                              void* d_out, int out_size)
{
    const float* x   = (const float*)d_in[0];
    const float* Wq  = (const float*)d_in[1];
    const float* bq  = (const float*)d_in[2];
    const float* Wk  = (const float*)d_in[3];
    const float* bk  = (const float*)d_in[4];
    const float* Wv  = (const float*)d_in[5];
    const float* bv  = (const float*)d_in[6];
    const float* Wo  = (const float*)d_in[7];
    const float* bo  = (const float*)d_in[8];
    const float* W1  = (const float*)d_in[9];
    const float* b1  = (const float*)d_in[10];
    const float* W2  = (const float*)d_in[11];
    const float* b2  = (const float*)d_in[12];
    const float* g1  = (const float*)d_in[13];
    const float* be1 = (const float*)d_in[14];
    const float* g2  = (const float*)d_in[15];
    const float* be2 = (const float*)d_in[16];
    float* out = (float*)d_out;

    bf16 *xph, *xpl, *qh, *kh, *vh, *aoh, *hh, *ffh;
    bf16 *wqh, *wkh, *wvh, *woh, *w1h, *w2h;
    float *sb, *hbuf;
    cudaGetSymbolAddress((void**)&xph, g_xph); cudaGetSymbolAddress((void**)&xpl, g_xpl);
    cudaGetSymbolAddress((void**)&qh,  g_qh);  cudaGetSymbolAddress((void**)&kh,  g_kh);
    cudaGetSymbolAddress((void**)&vh,  g_vh);  cudaGetSymbolAddress((void**)&aoh, g_aoh);
    cudaGetSymbolAddress((void**)&sb,  g_s);   cudaGetSymbolAddress((void**)&hbuf, g_h);
    cudaGetSymbolAddress((void**)&hh,  g_hh);  cudaGetSymbolAddress((void**)&ffh, g_ffh);
    cudaGetSymbolAddress((void**)&wqh, g_wqh); cudaGetSymbolAddress((void**)&wkh, g_wkh);
    cudaGetSymbolAddress((void**)&wvh, g_wvh); cudaGetSymbolAddress((void**)&woh, g_woh);
    cudaGetSymbolAddress((void**)&w1h, g_w1h); cudaGetSymbolAddress((void**)&w2h, g_w2h);

    constexpr int GSMEM2  = 3 * 24576;   // 2-pass BK=32 stages
    constexpr int GSMEM64 = 3 * 32768;   // 1-pass BK=64 stages
    cudaFuncSetAttribute(gemm_tc<4, true, 2, 32>,  cudaFuncAttributeMaxDynamicSharedMemorySize, GSMEM2);
    cudaFuncSetAttribute(gemm_tc<4, true, 1, 64>,  cudaFuncAttributeMaxDynamicSharedMemorySize, GSMEM64);
    cudaFuncSetAttribute(gemm_tc<1, false, 1, 64>, cudaFuncAttributeMaxDynamicSharedMemorySize, GSMEM64);
    cudaFuncSetAttribute(gemm_tc<2, false, 1, 64>, cudaFuncAttributeMaxDynamicSharedMemorySize, GSMEM64);
    cudaFuncSetAttribute(attn_tc, cudaFuncAttributeMaxDynamicSharedMemorySize, ATT_SMEM);

    padcvt_x<<<(BN_ * SP * D) / 256, 256>>>(x, xph, xpl);
    wtall<<<1024, dim3(32, 8)>>>(Wq, Wk, Wv, Wo, W1, W2, wqh, wkh, wvh, woh, w1h, w2h);

    const dim3 gQK(D / 128, TOK / 128, 2);
    const dim3 gD (D / 128, TOK / 128);
    const dim3 gF (Fd / 128, TOK / 128);
    const float qscale = 0.17677669529663687f;   // 1/sqrt(32)

    // Q+K fused (3-tap conv, 2-pass, BK=32, hi out; Q pre-scaled; ldB = 3*D)
    gemm_tc<4, true, 2, 32><<<gQK, 256, GSMEM2>>>(xph, xpl, D, wqh, 3 * D, D, 3, 0, qscale,
                                                  bq, nullptr, nullptr, qh, D,
                                                  wkh, bk, 1.f, kh);
    // V (1-pass, BK=64, hi out)
    gemm_tc<4, true, 1, 64><<<gD, 256, GSMEM64>>>(xph, nullptr, D, wvh, D, D, 1, 1, 1.f,
                                                  bv, nullptr, nullptr, vh, D,
                                                  nullptr, nullptr, 0.f, nullptr);
    // attention (single-pass bf16)
    attn_tc<<<Bd * S1 * Hh, 256, ATT_SMEM>>>(qh, kh, vh, aoh);
    // s = x + ao@Wo + bo (1-pass, BK=64)
    gemm_tc<1, false, 1, 64><<<gD, 256, GSMEM64>>>(aoh, nullptr, D, woh, D, D, 1, 0, 1.f,
                                                   bo, x, sb, nullptr, D,
                                                   nullptr, nullptr, 0.f, nullptr);
    ln_k<true><<<TOK / 8, 256>>>(sb, g1, be1, hbuf, hh);
    // ff = leaky(h@W1 + b1) (1-pass, BK=64, hi out)
    gemm_tc<2, false, 1, 64><<<gF, 256, GSMEM64>>>(hh, nullptr, D, w1h, D, D, 1, 0, 1.f,
                                                   b1, nullptr, nullptr, ffh, Fd,
                                                   nullptr, nullptr, 0.f, nullptr);
    // s = h + ff@W2 + b2 (1-pass, BK=64)
    gemm_tc<1, false, 1, 64><<<gD, 256, GSMEM64>>>(ffh, nullptr, Fd, w2h, Fd, Fd, 1, 0, 1.f,
                                                   b2, hbuf, sb, nullptr, D,
                                                   nullptr, nullptr, 0.f, nullptr);
    ln_k<false><<<TOK / 8, 256>>>(sb, g2, be2, out, nullptr);
}

// round 13
// speedup vs baseline: 2.5019x; 1.1820x over previous
#include <cuda_runtime.h>
#include <cuda_bf16.h>
#include <cstdint>
#include <math.h>

using bf16 = __nv_bfloat16;

// ---------------- problem constants ----------------
constexpr int Bd  = 4;
constexpr int S1  = 64;
constexpr int S2  = 256;
constexpr int D   = 256;
constexpr int Hh  = 8;
constexpr int HD  = 32;
constexpr int Fd  = 1024;
constexpr int TOK = Bd * S1 * S2;     // 65536
constexpr int BN_ = Bd * S1;          // 256
constexpr int SP  = S2 + 2;           // padded time length 258

// ---------------- scratch (device globals) ----------------
__device__ bf16  g_xph[BN_ * SP * D];
__device__ bf16  g_qh [TOK * D];
__device__ bf16  g_kh [TOK * D];
__device__ bf16  g_vh [TOK * D];
__device__ bf16  g_aoh[TOK * D];
__device__ float g_s  [TOK * D];
__device__ float g_h  [TOK * D];
__device__ bf16  g_hh [TOK * D];
__device__ bf16  g_ffh[TOK * Fd];
// transposed weights (hi only)
__device__ bf16 g_wqh[D * 3 * D];
__device__ bf16 g_wkh[D * 3 * D];
__device__ bf16 g_wvh[D * D];
__device__ bf16 g_woh[D * D];
__device__ bf16 g_w1h[Fd * D];
__device__ bf16 g_w2h[D * Fd];

// ---------------- helpers ----------------
__device__ __forceinline__ uint32_t smem_to_u32(const void* p) {
    uint32_t a;
    asm("{ .reg .u64 t; cvta.to.shared.u64 t, %1; cvt.u32.u64 %0, t; }" : "=r"(a) : "l"(p));
    return a;
}
#define CP_ASYNC16(s, g) \
    asm volatile("cp.async.cg.shared.global [%0], [%1], 16;" :: "r"((uint32_t)(s)), "l"(g))
#define CP_ASYNC_COMMIT() asm volatile("cp.async.commit_group;" ::: "memory")

__device__ __forceinline__ void ldsm4(uint32_t addr, uint32_t& r0, uint32_t& r1,
                                      uint32_t& r2, uint32_t& r3) {
    asm volatile("ldmatrix.sync.aligned.m8n8.x4.shared.b16 {%0,%1,%2,%3}, [%4];"
                 : "=r"(r0), "=r"(r1), "=r"(r2), "=r"(r3) : "r"(addr));
}
__device__ __forceinline__ void ldsm4t(uint32_t addr, uint32_t& r0, uint32_t& r1,
                                       uint32_t& r2, uint32_t& r3) {
    asm volatile("ldmatrix.sync.aligned.m8n8.x4.trans.shared.b16 {%0,%1,%2,%3}, [%4];"
                 : "=r"(r0), "=r"(r1), "=r"(r2), "=r"(r3) : "r"(addr));
}
__device__ __forceinline__ void mma_bf16(float* c, const uint32_t* a, const uint32_t* b) {
    asm volatile("mma.sync.aligned.m16n8k16.row.col.f32.bf16.bf16.f32 "
                 "{%0,%1,%2,%3}, {%4,%5,%6,%7}, {%8,%9}, {%0,%1,%2,%3};"
                 : "+f"(c[0]), "+f"(c[1]), "+f"(c[2]), "+f"(c[3])
                 : "r"(a[0]), "r"(a[1]), "r"(a[2]), "r"(a[3]), "r"(b[0]), "r"(b[1]));
}
__device__ __forceinline__ uint32_t pack2(bf16 a, bf16 b) {
    __nv_bfloat162 p; p.x = a; p.y = b;
    return *(uint32_t*)&p;
}
// 128B-row swizzle (BK=64): 8 16B cols, XOR by row&7 (SW128)
__device__ __forceinline__ uint32_t sw128r(int row, int c) {
    return (uint32_t)(row * 128 + ((c ^ (row & 7)) << 4));
}

// ---------------------------------------------------------------------------
// Tensor-core GEMM via mma.sync bf16, 128x128 block tile, BK=64, 1-pass,
// 3-stage cp.async pipeline, 2 CTAs/SM. gridDim.z == 2 -> blockIdx.z picks
// second weight/bias/output set (used to fuse Q and K).
// stage (32KB): [Ah 16K][Bh 16K] (128B rows, sw128r)
// EPI: 1 = bias*scl + R -> fp32 ; 2 = bias*scl + leaky -> bf16 hi ;
//      4 = bias*scl -> bf16 hi
// ---------------------------------------------------------------------------
constexpr int GSTAGE = 32768;
constexpr int GSMEM  = 3 * GSTAGE;   // 98304

template<int EPI, bool CONV>
__global__ __launch_bounds__(256, 2)
void gemm_tc(const bf16* __restrict__ Ah, int ldA,
             const bf16* Bh_, int ldB,
             int Ktap, int ntaps, int tapbase, float scl_,
             const float* bias_, const float* __restrict__ R,
             float* __restrict__ Cf, bf16* Ch_, int Nt,
             const bf16* Bh2, const float* bias2, float scl2, bf16* Ch2)
{
    extern __shared__ char smem[];
    const uint32_t sbase = smem_to_u32(smem);
    const int tid = threadIdx.x, wid = tid >> 5, lane = tid & 31;
    const int m0 = blockIdx.y * 128, n0 = blockIdx.x * 128;

    const bf16* Bh = Bh_;
    const float* bias = bias_;  float scl = scl_;
    bf16* Ch = Ch_;
    if (blockIdx.z == 1) { Bh = Bh2; bias = bias2; scl = scl2; Ch = Ch2; }

    int rowbase;
    if (CONV) { const int bn = m0 >> 8; const int t0 = m0 & 255; rowbase = bn * SP + t0 + tapbase; }
    else      { rowbase = m0; }

    const int kcpt = Ktap >> 6;          // 64-wide chunks per tap
    const int nch  = ntaps * kcpt;
    const int c8   = tid & 7;            // 16B col 0..7
    const int rw   = tid >> 3;           // row 0..31

    auto load_chunk = [&](int c, int stage) {
        const int tap = c / kcpt;
        const int kt  = (c - tap * kcpt) << 6;
        const size_t aoff = (size_t)(rowbase + tap) * ldA + kt + c8 * 8;
        const size_t boff = (size_t)n0 * ldB + (size_t)tap * Ktap + kt + c8 * 8;
        const uint32_t st = sbase + stage * GSTAGE;
#pragma unroll
        for (int i = 0; i < 4; i++) {
            const int row = rw + i * 32;
            const uint32_t so = sw128r(row, c8);
            CP_ASYNC16(st +         so, Ah + aoff + (size_t)row * ldA);
            CP_ASYNC16(st + 16384 + so, Bh + boff + (size_t)row * ldB);
        }
        CP_ASYNC_COMMIT();
    };

    load_chunk(0, 0);
    load_chunk(1, 1);

    const int wm  = wid & 1,  wn  = wid >> 1;
    const int m0w = wm * 64,  n0w = wn * 32;
    const int tq  = lane >> 3, rin = lane & 7;
    const int aRow = m0w + (tq & 1) * 8 + rin;
    const int akh  = tq >> 1;
    const int bRow = n0w + (tq >> 1) * 8 + rin;
    const int bkh  = tq & 1;

    float acc[4][4][4];
#pragma unroll
    for (int i = 0; i < 4; i++)
#pragma unroll
        for (int j = 0; j < 4; j++)
#pragma unroll
            for (int r = 0; r < 4; r++) acc[i][j][r] = 0.f;

    for (int c = 0; c < nch; c++) {
        if (c + 1 < nch) asm volatile("cp.async.wait_group 1;" ::: "memory");
        else             asm volatile("cp.async.wait_group 0;" ::: "memory");
        __syncthreads();
        if (c + 2 < nch) load_chunk(c + 2, (c + 2) % 3);

        const uint32_t Ab = sbase + (c % 3) * GSTAGE;
        const uint32_t Bb = Ab + 16384;

#pragma unroll
        for (int ks = 0; ks < 4; ks++) {
            uint32_t ah[4][4], bh[4][2];
#pragma unroll
            for (int mt = 0; mt < 4; mt++) {
                const int r = aRow + mt * 16;   // r & 7 == rin
                const uint32_t ad = Ab + (uint32_t)(r * 128)
                                  + (uint32_t)((((ks * 2 + akh) ^ rin) & 7) << 4);
                ldsm4(ad, ah[mt][0], ah[mt][1], ah[mt][2], ah[mt][3]);
            }
#pragma unroll
            for (int nt2 = 0; nt2 < 2; nt2++) {
                const int r = bRow + nt2 * 16;  // r & 7 == rin
                const uint32_t bd = Bb + (uint32_t)(r * 128)
                                  + (uint32_t)((((ks * 2 + bkh) ^ rin) & 7) << 4);
                uint32_t r0, r1, r2, r3;
                ldsm4(bd, r0, r1, r2, r3);
                bh[nt2 * 2][0] = r0; bh[nt2 * 2][1] = r1;
                bh[nt2 * 2 + 1][0] = r2; bh[nt2 * 2 + 1][1] = r3;
            }
#pragma unroll
            for (int mt = 0; mt < 4; mt++)
#pragma unroll
                for (int nt = 0; nt < 4; nt++)
                    mma_bf16(acc[mt][nt], ah[mt], bh[nt]);
        }
    }

    const int erow = lane >> 2;
    const int ecol = (lane & 3) * 2;
#pragma unroll
    for (int mt = 0; mt < 4; mt++) {
#pragma unroll
        for (int nt = 0; nt < 4; nt++) {
            const int col = n0 + n0w + nt * 8 + ecol;
            const float2 bi = *(const float2*)&bias[col];
#pragma unroll
            for (int half = 0; half < 2; half++) {
                const int row = m0 + m0w + mt * 16 + erow + half * 8;
                float v0 = (acc[mt][nt][half * 2 + 0] + bi.x) * scl;
                float v1 = (acc[mt][nt][half * 2 + 1] + bi.y) * scl;
                if (EPI == 1) {
                    const float2 rr = *(const float2*)&R[(size_t)row * Nt + col];
                    v0 += rr.x; v1 += rr.y;
                    float2 o; o.x = v0; o.y = v1;
                    *(float2*)&Cf[(size_t)row * Nt + col] = o;
                } else {
                    if (EPI == 2) {
                        v0 = v0 > 0.f ? v0 : 0.01f * v0;
                        v1 = v1 > 0.f ? v1 : 0.01f * v1;
                    }
                    *(uint32_t*)&Ch[(size_t)row * Nt + col] =
                        pack2(__float2bfloat16(v0), __float2bfloat16(v1));
                }
            }
        }
    }
}

// ---------------------------------------------------------------------------
// pad + convert x into bf16 padded buffer [bn][258][256]
// ---------------------------------------------------------------------------
__global__ __launch_bounds__(256)
void padcvt_x(const float* __restrict__ x, bf16* __restrict__ xh)
{
    const size_t i = (size_t)blockIdx.x * 256 + threadIdx.x;
    const int d = (int)(i & 255);
    const size_t rest = i >> 8;
    const int t = (int)(rest % SP);
    const size_t bn = rest / SP;
    float v = 0.f;
    if (t >= 1 && t <= S2) v = x[(bn * S2 + (t - 1)) * D + d];
    xh[i] = __float2bfloat16(v);
}

// ---------------------------------------------------------------------------
// fused weight transpose+convert (hi only): 6 weights in one launch
// ---------------------------------------------------------------------------
__global__ __launch_bounds__(256)
void wtall(const float* __restrict__ Wq, const float* __restrict__ Wk,
           const float* __restrict__ Wv, const float* __restrict__ Wo,
           const float* __restrict__ W1, const float* __restrict__ W2,
           bf16* wqh, bf16* wkh, bf16* wvh, bf16* woh, bf16* w1h, bf16* w2h)
{
    __shared__ float ts[32][33];
    const int t = blockIdx.x;
    const float* W; bf16* Bh; int K, N, lt;
    if      (t < 192) { W = Wq; Bh = wqh; K = 768;  N = 256;  lt = t; }
    else if (t < 384) { W = Wk; Bh = wkh; K = 768;  N = 256;  lt = t - 192; }
    else if (t < 448) { W = Wv; Bh = wvh; K = 256;  N = 256;  lt = t - 384; }
    else if (t < 512) { W = Wo; Bh = woh; K = 256;  N = 256;  lt = t - 448; }
    else if (t < 768) { W = W1; Bh = w1h; K = 256;  N = 1024; lt = t - 512; }
    else              { W = W2; Bh = w2h; K = 1024; N = 256;  lt = t - 768; }
    const int ntn = N / 32;
    const int n0 = (lt % ntn) * 32, k0 = (lt / ntn) * 32;
    const int tx = threadIdx.x, ty = threadIdx.y;   // 32 x 8
#pragma unroll
    for (int j = 0; j < 4; j++)
        ts[ty + j * 8][tx] = W[(size_t)(k0 + ty + j * 8) * N + n0 + tx];
    __syncthreads();
#pragma unroll
    for (int j = 0; j < 4; j++)
        Bh[(size_t)(n0 + ty + j * 8) * K + k0 + tx] = __float2bfloat16(ts[tx][ty + j * 8]);
}

// ---------------------------------------------------------------------------
// Flash attention on tensor cores, single-pass bf16 throughout.
// One block per (b,n,h); 8 warps x 32 rows. V B-frags via ldmatrix.x4.trans.
// smem: Qh Kh Vh, 3 x 20480 (rows stride 80B -> conflict-free)
// ---------------------------------------------------------------------------
constexpr int ATT_SMEM = 3 * 20480;   // 61440

__global__ __launch_bounds__(256, 2)
void attn_tc(const bf16* __restrict__ qh, const bf16* __restrict__ kh,
             const bf16* __restrict__ vh, bf16* __restrict__ oh)
{
    extern __shared__ char smem[];
    const uint32_t sb = smem_to_u32(smem);
    const uint32_t Qh = sb, Kh = sb + 20480, Vh = sb + 40960;

    const int tid = threadIdx.x, wid = tid >> 5, lane = tid & 31;
    const int h = blockIdx.x & 7, bn = blockIdx.x >> 3;
    const size_t gbase = (size_t)bn * 256 * 256 + h * 32;

    for (int idx = tid; idx < 1024; idx += 256) {
        const int row = idx >> 2, c = idx & 3;
        const size_t g = gbase + (size_t)row * 256 + c * 8;
        const uint32_t so = row * 80 + c * 16;
        CP_ASYNC16(Qh + so, qh + g);
        CP_ASYNC16(Kh + so, kh + g);
        CP_ASYNC16(Vh + so, vh + g);
    }
    CP_ASYNC_COMMIT();
    asm volatile("cp.async.wait_group 0;" ::: "memory");
    __syncthreads();

    const int tq = lane >> 3, rin = lane & 7;
    const int aR  = (tq & 1) * 8 + rin;
    const int akh = tq >> 1;
    const int bR  = (tq >> 1) * 8 + rin;
    const int bkh = tq & 1;
    const int vrow  = (lane & 7) + ((lane >> 3) & 1) * 8;
    const int vcolb = ((lane >> 4) & 1) * 16;

    uint32_t qf[2][2][4];
#pragma unroll
    for (int mt = 0; mt < 2; mt++)
#pragma unroll
        for (int ks = 0; ks < 2; ks++) {
            const uint32_t ad = Qh + (uint32_t)((wid * 32 + mt * 16 + aR) * 80)
                              + (uint32_t)((ks * 2 + akh) * 16);
            ldsm4(ad, qf[mt][ks][0], qf[mt][ks][1], qf[mt][ks][2], qf[mt][ks][3]);
        }

    float O[2][4][4];
#pragma unroll
    for (int mt = 0; mt < 2; mt++)
#pragma unroll
        for (int j = 0; j < 4; j++)
#pragma unroll
            for (int r = 0; r < 4; r++) O[mt][j][r] = 0.f;
    float mrow[2][2] = { {-1e30f, -1e30f}, {-1e30f, -1e30f} };
    float lrow[2][2] = { {0.f, 0.f}, {0.f, 0.f} };

    for (int s0 = 0; s0 < 256; s0 += 64) {
        float acc[2][8][4];
#pragma unroll
        for (int mt = 0; mt < 2; mt++)
#pragma unroll
            for (int j = 0; j < 8; j++)
#pragma unroll
                for (int r = 0; r < 4; r++) acc[mt][j][r] = 0.f;

#pragma unroll
        for (int ks = 0; ks < 2; ks++) {
            uint32_t kb[8][2];
#pragma unroll
            for (int g = 0; g < 4; g++) {
                const uint32_t kd = Kh + (uint32_t)((s0 + g * 16 + bR) * 80)
                                  + (uint32_t)((ks * 2 + bkh) * 16);
                uint32_t r0, r1, r2, r3;
                ldsm4(kd, r0, r1, r2, r3);
                kb[g * 2][0] = r0; kb[g * 2][1] = r1;
                kb[g * 2 + 1][0] = r2; kb[g * 2 + 1][1] = r3;
            }
#pragma unroll
            for (int mt = 0; mt < 2; mt++)
#pragma unroll
                for (int j = 0; j < 8; j++)
                    mma_bf16(acc[mt][j], qf[mt][ks], kb[j]);
        }

#pragma unroll
        for (int mt = 0; mt < 2; mt++) {
            float mxA = -1e30f, mxB = -1e30f;
#pragma unroll
            for (int j = 0; j < 8; j++) {
                mxA = fmaxf(mxA, fmaxf(acc[mt][j][0], acc[mt][j][1]));
                mxB = fmaxf(mxB, fmaxf(acc[mt][j][2], acc[mt][j][3]));
            }
            mxA = fmaxf(mxA, __shfl_xor_sync(0xffffffffu, mxA, 1));
            mxA = fmaxf(mxA, __shfl_xor_sync(0xffffffffu, mxA, 2));
            mxB = fmaxf(mxB, __shfl_xor_sync(0xffffffffu, mxB, 1));
            mxB = fmaxf(mxB, __shfl_xor_sync(0xffffffffu, mxB, 2));
            const float mnA = fmaxf(mrow[mt][0], mxA);
            const float mnB = fmaxf(mrow[mt][1], mxB);
            const float fA = __expf(mrow[mt][0] - mnA);
            const float fB = __expf(mrow[mt][1] - mnB);
            mrow[mt][0] = mnA; mrow[mt][1] = mnB;
            float sA = 0.f, sB = 0.f;
#pragma unroll
            for (int j = 0; j < 8; j++) {
                acc[mt][j][0] = __expf(acc[mt][j][0] - mnA);
                acc[mt][j][1] = __expf(acc[mt][j][1] - mnA);
                acc[mt][j][2] = __expf(acc[mt][j][2] - mnB);
                acc[mt][j][3] = __expf(acc[mt][j][3] - mnB);
                sA += acc[mt][j][0] + acc[mt][j][1];
                sB += acc[mt][j][2] + acc[mt][j][3];
            }
            lrow[mt][0] = lrow[mt][0] * fA + sA;
            lrow[mt][1] = lrow[mt][1] * fB + sB;
#pragma unroll
            for (int j = 0; j < 4; j++) {
                O[mt][j][0] *= fA; O[mt][j][1] *= fA;
                O[mt][j][2] *= fB; O[mt][j][3] *= fB;
            }
        }

#pragma unroll
        for (int kt = 0; kt < 4; kt++) {
            uint32_t vb[4][2];
#pragma unroll
            for (int nb = 0; nb < 2; nb++) {
                const uint32_t vd = Vh + (uint32_t)((s0 + kt * 16 + vrow) * 80)
                                  + (uint32_t)(nb * 32 + vcolb);
                uint32_t r0, r1, r2, r3;
                ldsm4t(vd, r0, r1, r2, r3);
                vb[nb * 2][0] = r0; vb[nb * 2][1] = r1;
                vb[nb * 2 + 1][0] = r2; vb[nb * 2 + 1][1] = r3;
            }
#pragma unroll
            for (int mt = 0; mt < 2; mt++) {
                uint32_t ph[4];
#pragma unroll
                for (int half = 0; half < 2; half++) {
                    const int j = 2 * kt + half;
                    ph[half * 2 + 0] = pack2(__float2bfloat16(acc[mt][j][0]),
                                             __float2bfloat16(acc[mt][j][1]));
                    ph[half * 2 + 1] = pack2(__float2bfloat16(acc[mt][j][2]),
                                             __float2bfloat16(acc[mt][j][3]));
                }
#pragma unroll
                for (int j2 = 0; j2 < 4; j2++)
                    mma_bf16(O[mt][j2], ph, vb[j2]);
            }
        }
    }

#pragma unroll
    for (int mt = 0; mt < 2; mt++) {
        float lA = lrow[mt][0], lB = lrow[mt][1];
        lA += __shfl_xor_sync(0xffffffffu, lA, 1);
        lA += __shfl_xor_sync(0xffffffffu, lA, 2);
        lB += __shfl_xor_sync(0xffffffffu, lB, 1);
        lB += __shfl_xor_sync(0xffffffffu, lB, 2);
        const float invA = 1.f / lA, invB = 1.f / lB;
        const int rowA = wid * 32 + mt * 16 + (lane >> 2);
        const size_t gA = gbase + (size_t)rowA * 256;
        const size_t gB = gA + (size_t)8 * 256;
#pragma unroll
        for (int j2 = 0; j2 < 4; j2++) {
            const int col = j2 * 8 + (lane & 3) * 2;
            *(uint32_t*)&oh[gA + col] = pack2(__float2bfloat16(O[mt][j2][0] * invA),
                                              __float2bfloat16(O[mt][j2][1] * invA));
            *(uint32_t*)&oh[gB + col] = pack2(__float2bfloat16(O[mt][j2][2] * invB),
                                              __float2bfloat16(O[mt][j2][3] * invB));
        }
    }
}

// ---------------------------------------------------------------------------
// LayerNorm (D=256). Optionally emits bf16 hi of the normalized output.
// ---------------------------------------------------------------------------
template<bool EMIT>
__global__ __launch_bounds__(256)
void ln_k(const float* __restrict__ X, const float* __restrict__ g,
          const float* __restrict__ be, float* __restrict__ Y,
          bf16* __restrict__ Yh)
{
    const int r    = blockIdx.x * 8 + (threadIdx.x >> 5);
    const int lane = threadIdx.x & 31;
    const float* xr = X + (long long)r * D;

    float xv[8];
    float s = 0.f, ss = 0.f;
#pragma unroll
    for (int j = 0; j < 8; j++) {
        const float t = xr[lane + j * 32];
        xv[j] = t; s += t; ss += t * t;
    }
#pragma unroll
    for (int ofs = 16; ofs > 0; ofs >>= 1) {
        s  += __shfl_xor_sync(0xffffffffu, s,  ofs);
        ss += __shfl_xor_sync(0xffffffffu, ss, ofs);
    }
    const float mu  = s * (1.f / 256.f);
    const float var = ss * (1.f / 256.f) - mu * mu;
    const float rs  = rsqrtf(var + 1e-5f);

#pragma unroll
    for (int j = 0; j < 8; j++) {
        const int d = lane + j * 32;
        const float y = (xv[j] - mu) * rs * g[d] + be[d];
        Y[(long long)r * D + d] = y;
        if (EMIT) Yh[(long long)r * D + d] = __float2bfloat16(y);
    }
}

// ---------------------------------------------------------------------------
extern "C" void kernel_launch(void* const* d_in, const int* in_sizes, int n_in,
                              void* d_out, int out_size)
{
    const float* x   = (const float*)d_in[0];
    const float* Wq  = (const float*)d_in[1];
    const float* bq  = (const float*)d_in[2];
    const float* Wk  = (const float*)d_in[3];
    const float* bk  = (const float*)d_in[4];
    const float* Wv  = (const float*)d_in[5];
    const float* bv  = (const float*)d_in[6];
    const float* Wo  = (const float*)d_in[7];
    const float* bo  = (const float*)d_in[8];
    const float* W1  = (const float*)d_in[9];
    const float* b1  = (const float*)d_in[10];
    const float* W2  = (const float*)d_in[11];
    const float* b2  = (const float*)d_in[12];
    const float* g1  = (const float*)d_in[13];
    const float* be1 = (const float*)d_in[14];
    const float* g2  = (const float*)d_in[15];
    const float* be2 = (const float*)d_in[16];
    float* out = (float*)d_out;

    bf16 *xph, *qh, *kh, *vh, *aoh, *hh, *ffh;
    bf16 *wqh, *wkh, *wvh, *woh, *w1h, *w2h;
    float *sb, *hbuf;
    cudaGetSymbolAddress((void**)&xph, g_xph);
    cudaGetSymbolAddress((void**)&qh,  g_qh);  cudaGetSymbolAddress((void**)&kh,  g_kh);
    cudaGetSymbolAddress((void**)&vh,  g_vh);  cudaGetSymbolAddress((void**)&aoh, g_aoh);
    cudaGetSymbolAddress((void**)&sb,  g_s);   cudaGetSymbolAddress((void**)&hbuf, g_h);
    cudaGetSymbolAddress((void**)&hh,  g_hh);  cudaGetSymbolAddress((void**)&ffh, g_ffh);
    cudaGetSymbolAddress((void**)&wqh, g_wqh); cudaGetSymbolAddress((void**)&wkh, g_wkh);
    cudaGetSymbolAddress((void**)&wvh, g_wvh); cudaGetSymbolAddress((void**)&woh, g_woh);
    cudaGetSymbolAddress((void**)&w1h, g_w1h); cudaGetSymbolAddress((void**)&w2h, g_w2h);

    cudaFuncSetAttribute(gemm_tc<4, true>,  cudaFuncAttributeMaxDynamicSharedMemorySize, GSMEM);
    cudaFuncSetAttribute(gemm_tc<1, false>, cudaFuncAttributeMaxDynamicSharedMemorySize, GSMEM);
    cudaFuncSetAttribute(gemm_tc<2, false>, cudaFuncAttributeMaxDynamicSharedMemorySize, GSMEM);
    cudaFuncSetAttribute(attn_tc, cudaFuncAttributeMaxDynamicSharedMemorySize, ATT_SMEM);

    padcvt_x<<<(BN_ * SP * D) / 256, 256>>>(x, xph);
    wtall<<<1024, dim3(32, 8)>>>(Wq, Wk, Wv, Wo, W1, W2, wqh, wkh, wvh, woh, w1h, w2h);

    const dim3 gQK(D / 128, TOK / 128, 2);
    const dim3 gD (D / 128, TOK / 128);
    const dim3 gF (Fd / 128, TOK / 128);
    const float qscale = 0.17677669529663687f;   // 1/sqrt(32)

    // Q+K fused (3-tap conv, 1-pass, BK=64, hi out; Q pre-scaled; ldB = 3*D)
    gemm_tc<4, true><<<gQK, 256, GSMEM>>>(xph, D, wqh, 3 * D, D, 3, 0, qscale,
                                          bq, nullptr, nullptr, qh, D,
                                          wkh, bk, 1.f, kh);
    // V (1-pass, BK=64, hi out; center tap)
    gemm_tc<4, true><<<gD, 256, GSMEM>>>(xph, D, wvh, D, D, 1, 1, 1.f,
                                         bv, nullptr, nullptr, vh, D,
                                         nullptr, nullptr, 0.f, nullptr);
    // attention (single-pass bf16)
    attn_tc<<<Bd * S1 * Hh, 256, ATT_SMEM>>>(qh, kh, vh, aoh);
    // s = x + ao@Wo + bo
    gemm_tc<1, false><<<gD, 256, GSMEM>>>(aoh, D, woh, D, D, 1, 0, 1.f,
                                          bo, x, sb, nullptr, D,
                                          nullptr, nullptr, 0.f, nullptr);
    ln_k<true><<<TOK / 8, 256>>>(sb, g1, be1, hbuf, hh);
    // ff = leaky(h@W1 + b1)
    gemm_tc<2, false><<<gF, 256, GSMEM>>>(hh, D, w1h, D, D, 1, 0, 1.f,
                                          b1, nullptr, nullptr, ffh, Fd,
                                          nullptr, nullptr, 0.f, nullptr);
    // s = h + ff@W2 + b2
    gemm_tc<1, false><<<gD, 256, GSMEM>>>(ffh, Fd, w2h, Fd, Fd, 1, 0, 1.f,
                                          b2, hbuf, sb, nullptr, D,
                                          nullptr, nullptr, 0.f, nullptr);
    ln_k<false><<<TOK / 8, 256>>>(sb, g2, be2, out, nullptr);
}